// round 1
// baseline (speedup 1.0000x reference)
#include <cuda_runtime.h>
#include <cstddef>

#define NN 15872
#define DD 129
#define HH 128
#define KK 132   // padded per-edge input: 129 nbr + 1 iou + 2 zero pad

static __device__ float g_interp[NN * DD];
static __device__ float g_pooled[NN * HH];
static __device__ int   g_segstart[NN + 1];

// ---------------------------------------------------------------------------
// Prefix scan of neighborhood_sizes -> segment start offsets (single block).
// ---------------------------------------------------------------------------
__global__ void scan_kernel(const int* __restrict__ sizes) {
    __shared__ int sh[1024];
    const int PER = 16;                    // 1024*16 = 16384 >= NN
    int tid = threadIdx.x;
    int local[PER];
    int s = 0;
    int base = tid * PER;
#pragma unroll
    for (int i = 0; i < PER; i++) {
        int idx = base + i;
        int v = (idx < NN) ? sizes[idx] : 0;
        local[i] = s;
        s += v;
    }
    sh[tid] = s;
    __syncthreads();
    // Hillis-Steele inclusive scan over 1024 partials
    for (int off = 1; off < 1024; off <<= 1) {
        int v = 0;
        if (tid >= off) v = sh[tid - off];
        __syncthreads();
        if (tid >= off) sh[tid] += v;
        __syncthreads();
    }
    int excl = (tid == 0) ? 0 : sh[tid - 1];
#pragma unroll
    for (int i = 0; i < PER; i++) {
        int idx = base + i;
        if (idx <= NN) g_segstart[idx] = excl + local[i];
    }
}

// ---------------------------------------------------------------------------
// Edge MLP + per-segment max pool.
// 256 threads = 2 independent groups of 128; each group owns one segment at a
// time. Weights live in SMEM (shared by both groups). Each thread owns hidden
// unit t = tid&127 and register-tiles 8 edges.
// The "main" half of layer-1 input is constant per segment -> precomputed
// into a per-thread scalar `base` once per segment.
// ---------------------------------------------------------------------------
extern __shared__ float smem[];

__global__ void __launch_bounds__(256, 1)
edge_kernel(const float* __restrict__ src,       // (NN, DD) source features
            const float* __restrict__ add_info,  // (E, 1)
            const int*   __restrict__ nbr_idx,   // (E,)
            const int*   __restrict__ self_idx,  // (E,)
            const float* __restrict__ W1,        // (259, 128)
            const float* __restrict__ b1,        // (128,)
            const float* __restrict__ W2,        // (128, 128)
            const float* __restrict__ b2)        // (128,)
{
    float* W1n = smem;                 // KK x HH  (nbr rows 0..128, iou row, 2 zero rows)
    float* W1m = W1n + KK * HH;        // DD x HH  (main rows 129..257)
    float* W2s = W1m + DD * HH;        // HH x HH
    float* grp = W2s + HH * HH;
    const int GSZ = 8 * KK + 8 * HH + KK;   // xs + h1s + mains per group

    int tid = threadIdx.x;

    // Cooperative weight staging (all 256 threads)
    for (int i = tid; i < KK * HH; i += 256) {
        int k = i >> 7, t = i & 127;
        float v = 0.f;
        if (k < DD) v = W1[k * HH + t];
        else if (k == DD) v = W1[(2 * DD) * HH + t];   // iou row = 258
        W1n[i] = v;
    }
    for (int i = tid; i < DD * HH; i += 256) {
        int k = i >> 7, t = i & 127;
        W1m[i] = W1[(DD + k) * HH + t];                // rows 129..257
    }
    for (int i = tid; i < HH * HH; i += 256) W2s[i] = W2[i];
    __syncthreads();

    const int g  = tid >> 7;
    const int gt = tid & 127;
    float* xs    = grp + g * GSZ;          // 8 x KK (row stride 132 floats, 16B aligned)
    float* h1s   = xs + 8 * KK;            // 8 x HH
    float* mains = h1s + 8 * HH;           // KK

    const float bb1 = b1[gt];
    const float bb2 = b2[gt];

    for (int seg = blockIdx.x * 2 + g; seg < NN; seg += gridDim.x * 2) {
        int s0  = g_segstart[seg];
        int cnt = g_segstart[seg + 1] - s0;
        int self = self_idx[s0];

        for (int i = gt; i < KK; i += 128)
            mains[i] = (i < DD) ? src[(size_t)self * DD + i] : 0.f;
        asm volatile("bar.sync %0, 128;" :: "r"(g + 1) : "memory");

        // per-segment base = b1[t] + sum_j main[j] * W1[129+j][t]
        float p0 = 0.f, p1 = 0.f, p2 = 0.f, p3 = 0.f;
#pragma unroll 4
        for (int j = 0; j < 128; j += 4) {
            p0 = fmaf(mains[j + 0], W1m[(j + 0) * HH + gt], p0);
            p1 = fmaf(mains[j + 1], W1m[(j + 1) * HH + gt], p1);
            p2 = fmaf(mains[j + 2], W1m[(j + 2) * HH + gt], p2);
            p3 = fmaf(mains[j + 3], W1m[(j + 3) * HH + gt], p3);
        }
        float base = bb1 + ((p0 + p1) + (p2 + p3)) + mains[128] * W1m[128 * HH + gt];

        float mx = -3.4e38f;

        for (int eb = 0; eb < cnt; eb += 8) {
            int ne = cnt - eb;
            if (ne > 8) ne = 8;

            // Stage x = [nbr(129) | iou(1) | pad(2)] for up to 8 edges
            for (int i = gt; i < ne * KK; i += 128) {
                int e = i / KK;
                int k = i - e * KK;
                int edge = s0 + eb + e;
                float v;
                if (k < DD)       v = src[(size_t)nbr_idx[edge] * DD + k];
                else if (k == DD) v = add_info[edge];
                else              v = 0.f;
                xs[e * KK + k] = v;
            }
            asm volatile("bar.sync %0, 128;" :: "r"(g + 1) : "memory");   // S1

            // Layer 1: acc[e] = base + sum_k xs[e][k] * W1n[k][t]
            float acc[8];
#pragma unroll
            for (int e = 0; e < 8; e++) acc[e] = base;
            for (int k = 0; k < KK; k += 4) {
                float w0 = W1n[(k + 0) * HH + gt];
                float w1 = W1n[(k + 1) * HH + gt];
                float w2 = W1n[(k + 2) * HH + gt];
                float w3 = W1n[(k + 3) * HH + gt];
#pragma unroll
                for (int e = 0; e < 8; e++) {
                    float4 xv = *reinterpret_cast<const float4*>(&xs[e * KK + k]);
                    acc[e] = fmaf(xv.x, w0, acc[e]);
                    acc[e] = fmaf(xv.y, w1, acc[e]);
                    acc[e] = fmaf(xv.z, w2, acc[e]);
                    acc[e] = fmaf(xv.w, w3, acc[e]);
                }
            }
#pragma unroll
            for (int e = 0; e < 8; e++) h1s[e * HH + gt] = fmaxf(acc[e], 0.f);
            asm volatile("bar.sync %0, 128;" :: "r"(g + 1) : "memory");   // S2

            // Layer 2: acc2[e] = b2[t] + sum_j h1[e][j] * W2[j][t]
            float acc2[8];
#pragma unroll
            for (int e = 0; e < 8; e++) acc2[e] = bb2;
            for (int j = 0; j < HH; j += 4) {
                float w0 = W2s[(j + 0) * HH + gt];
                float w1 = W2s[(j + 1) * HH + gt];
                float w2 = W2s[(j + 2) * HH + gt];
                float w3 = W2s[(j + 3) * HH + gt];
#pragma unroll
                for (int e = 0; e < 8; e++) {
                    float4 hv = *reinterpret_cast<const float4*>(&h1s[e * HH + j]);
                    acc2[e] = fmaf(hv.x, w0, acc2[e]);
                    acc2[e] = fmaf(hv.y, w1, acc2[e]);
                    acc2[e] = fmaf(hv.z, w2, acc2[e]);
                    acc2[e] = fmaf(hv.w, w3, acc2[e]);
                }
            }
#pragma unroll
            for (int e = 0; e < 8; e++)
                if (e < ne) mx = fmaxf(mx, fmaxf(acc2[e], 0.f));
        }

        g_pooled[(size_t)seg * HH + gt] = mx;
    }
}

// ---------------------------------------------------------------------------
// g_interp[n] = src[n] + bo + pooled[n] @ Wo     (Wo: 128 x 129)
// ---------------------------------------------------------------------------
__global__ void __launch_bounds__(256)
wo_kernel(const float* __restrict__ src,
          const float* __restrict__ Wo,
          const float* __restrict__ bo)
{
    extern __shared__ float sm[];
    float* Wos = sm;                 // HH * DD
    float* ps  = Wos + HH * DD;      // 16 * HH
    int tid = threadIdx.x;
    for (int i = tid; i < HH * DD; i += 256) Wos[i] = Wo[i];

    int rb = blockIdx.x * 16;
    __syncthreads();
    for (int i = tid; i < 16 * HH; i += 256) {
        int r = i >> 7;
        ps[i] = g_pooled[(size_t)(rb + r) * HH + (i & 127)];
    }
    __syncthreads();
    for (int i = tid; i < 16 * DD; i += 256) {
        int r = i / DD, c = i - r * DD;
        const float* pr = &ps[r * HH];
        float a0 = 0.f, a1 = 0.f, a2 = 0.f, a3 = 0.f;
#pragma unroll 4
        for (int j = 0; j < HH; j += 4) {
            a0 = fmaf(pr[j + 0], Wos[(j + 0) * DD + c], a0);
            a1 = fmaf(pr[j + 1], Wos[(j + 1) * DD + c], a1);
            a2 = fmaf(pr[j + 2], Wos[(j + 2) * DD + c], a2);
            a3 = fmaf(pr[j + 3], Wos[(j + 3) * DD + c], a3);
        }
        size_t o = (size_t)(rb + r) * DD + c;
        g_interp[o] = src[o] + bo[c] + ((a0 + a1) + (a2 + a3));
    }
}

// ---------------------------------------------------------------------------
// out[n] = relu(g_interp[n] @ fW1 + fb1) @ fW2 + fb2   (129 -> 64 -> 1)
// one warp per row
// ---------------------------------------------------------------------------
__global__ void __launch_bounds__(256)
final_kernel(const float* __restrict__ fW1, const float* __restrict__ fb1,
             const float* __restrict__ fW2, const float* __restrict__ fb2,
             float* __restrict__ out)
{
    __shared__ float W1s[DD * 64];
    __shared__ float w2s[64];
    __shared__ float b1s[64];
    int tid = threadIdx.x;
    for (int i = tid; i < DD * 64; i += 256) W1s[i] = fW1[i];
    if (tid < 64) { w2s[tid] = fW2[tid]; b1s[tid] = fb1[tid]; }
    __syncthreads();
    float fb2v = fb2[0];
    int warp = tid >> 5, lane = tid & 31;
    int n = blockIdx.x * 8 + warp;
    if (n >= NN) return;
    const float* row = g_interp + (size_t)n * DD;
    float h0 = b1s[lane], h1 = b1s[lane + 32];
    for (int k = 0; k < DD; k++) {
        float x = row[k];
        h0 = fmaf(x, W1s[k * 64 + lane],      h0);
        h1 = fmaf(x, W1s[k * 64 + lane + 32], h1);
    }
    float v = fmaxf(h0, 0.f) * w2s[lane] + fmaxf(h1, 0.f) * w2s[lane + 32];
#pragma unroll
    for (int off = 16; off; off >>= 1)
        v += __shfl_down_sync(0xffffffffu, v, off);
    if (lane == 0) out[n] = v + fb2v;
}

// ---------------------------------------------------------------------------
extern "C" void kernel_launch(void* const* d_in, const int* in_sizes, int n_in,
                              void* d_out, int out_size)
{
    (void)in_sizes; (void)n_in; (void)out_size;

    const float* interp_in = (const float*)d_in[0];
    const float* add_info  = (const float*)d_in[1];
    const int*   sizes     = (const int*)d_in[2];
    const int*   nbr       = (const int*)d_in[3];
    const int*   self      = (const int*)d_in[4];
    const float* b0W1 = (const float*)d_in[5];
    const float* b0b1 = (const float*)d_in[6];
    const float* b0W2 = (const float*)d_in[7];
    const float* b0b2 = (const float*)d_in[8];
    const float* b0Wo = (const float*)d_in[9];
    const float* b0bo = (const float*)d_in[10];
    const float* b1W1 = (const float*)d_in[11];
    const float* b1b1 = (const float*)d_in[12];
    const float* b1W2 = (const float*)d_in[13];
    const float* b1b2 = (const float*)d_in[14];
    const float* b1Wo = (const float*)d_in[15];
    const float* b1bo = (const float*)d_in[16];
    const float* fW1  = (const float*)d_in[17];
    const float* fb1  = (const float*)d_in[18];
    const float* fW2  = (const float*)d_in[19];
    const float* fb2  = (const float*)d_in[20];
    float* out = (float*)d_out;

    float* ginterp = nullptr;
    cudaGetSymbolAddress((void**)&ginterp, g_interp);

    int nsm = 148;
    cudaDeviceGetAttribute(&nsm, cudaDevAttrMultiProcessorCount, 0);

    size_t edge_smem = (size_t)(KK * HH + DD * HH + HH * HH +
                                2 * (8 * KK + 8 * HH + KK)) * sizeof(float);
    cudaFuncSetAttribute(edge_kernel,
                         cudaFuncAttributeMaxDynamicSharedMemorySize,
                         (int)edge_smem);
    size_t wo_smem = (size_t)(HH * DD + 16 * HH) * sizeof(float);
    cudaFuncSetAttribute(wo_kernel,
                         cudaFuncAttributeMaxDynamicSharedMemorySize,
                         (int)wo_smem);

    scan_kernel<<<1, 1024>>>(sizes);

    // block 0
    edge_kernel<<<nsm, 256, edge_smem>>>(interp_in, add_info, nbr, self,
                                         b0W1, b0b1, b0W2, b0b2);
    wo_kernel<<<NN / 16, 256, wo_smem>>>(interp_in, b0Wo, b0bo);

    // block 1
    edge_kernel<<<nsm, 256, edge_smem>>>(ginterp, add_info, nbr, self,
                                         b1W1, b1b1, b1W2, b1b2);
    wo_kernel<<<NN / 16, 256, wo_smem>>>(ginterp, b1Wo, b1bo);

    // final scorer
    final_kernel<<<NN / 8, 256>>>(fW1, fb1, fW2, fb2, out);
}

// round 2
// speedup vs baseline: 1.1942x; 1.1942x over previous
#include <cuda_runtime.h>
#include <cstddef>

#define NN 15872
#define DD 129
#define HH 128
#define KK 132   // padded per-edge input: 129 nbr + 1 iou + 2 zero pad

static __device__ float g_interp[NN * DD];
static __device__ float g_pooled[NN * HH];
static __device__ float g_base[NN * HH];
static __device__ int   g_segstart[NN + 1];

// ---------------------------------------------------------------------------
// Prefix scan of neighborhood_sizes -> segment start offsets (single block).
// ---------------------------------------------------------------------------
__global__ void scan_kernel(const int* __restrict__ sizes) {
    __shared__ int sh[1024];
    const int PER = 16;                    // 1024*16 = 16384 >= NN
    int tid = threadIdx.x;
    int local[PER];
    int s = 0;
    int base = tid * PER;
#pragma unroll
    for (int i = 0; i < PER; i++) {
        int idx = base + i;
        int v = (idx < NN) ? sizes[idx] : 0;
        local[i] = s;
        s += v;
    }
    sh[tid] = s;
    __syncthreads();
    for (int off = 1; off < 1024; off <<= 1) {
        int v = 0;
        if (tid >= off) v = sh[tid - off];
        __syncthreads();
        if (tid >= off) sh[tid] += v;
        __syncthreads();
    }
    int excl = (tid == 0) ? 0 : sh[tid - 1];
#pragma unroll
    for (int i = 0; i < PER; i++) {
        int idx = base + i;
        if (idx <= NN) g_segstart[idx] = excl + local[i];
    }
}

// ---------------------------------------------------------------------------
// base[n][t] = b1[t] + sum_j src[n][j] * W1[129+j][t]
// (the layer-1 contribution of the segment-constant "main" features)
// ---------------------------------------------------------------------------
__global__ void __launch_bounds__(256)
base_kernel(const float* __restrict__ src,
            const float* __restrict__ W1,
            const float* __restrict__ b1)
{
    extern __shared__ float sm[];
    float* Wm   = sm;              // DD x HH  (rows 129..257 of W1)
    float* xsrc = Wm + DD * HH;    // 16 x DD
    int tid = threadIdx.x;
    for (int i = tid; i < DD * HH; i += 256) Wm[i] = W1[DD * HH + i];
    int rb = blockIdx.x * 16;
    for (int i = tid; i < 16 * DD; i += 256) {
        int r = i / DD, c = i - r * DD;
        xsrc[i] = src[(size_t)(rb + r) * DD + c];
    }
    __syncthreads();
    int t = tid & 127, p = tid >> 7;
    float acc[8];
    float bb = b1[t];
#pragma unroll
    for (int i = 0; i < 8; i++) acc[i] = bb;
    for (int j = 0; j < DD; j++) {
        float w = Wm[j * HH + t];
#pragma unroll
        for (int i = 0; i < 8; i++)
            acc[i] = fmaf(xsrc[(p + 2 * i) * DD + j], w, acc[i]);
    }
#pragma unroll
    for (int i = 0; i < 8; i++)
        g_base[(size_t)(rb + p + 2 * i) * HH + t] = acc[i];
}

// ---------------------------------------------------------------------------
// Edge MLP + per-segment max pool. 512 threads = 4 independent groups of 128.
// Thread owns hidden unit t; register-tiles 8 edges. Layer-1 accumulators are
// seeded from the precomputed g_base table. Next chunk's gathers are
// prefetched into registers during compute (double-buffered via regs).
// ---------------------------------------------------------------------------
__device__ __forceinline__ void prefetch_chunk(const float* __restrict__ src,
                                               const float* __restrict__ add_info,
                                               const int*   __restrict__ nbr,
                                               int e0, int ne, int gt, float* pf)
{
#pragma unroll
    for (int r = 0; r < 9; r++) {
        int idx = gt + (r << 7);
        float v = 0.f;
        if (r < 8 || gt < 32) {            // idx < 8*132 = 1056
            int e = idx / KK;
            int k = idx - e * KK;
            if (e < ne) {
                if (k < DD)       v = __ldg(&src[(size_t)nbr[e0 + e] * DD + k]);
                else if (k == DD) v = __ldg(&add_info[e0 + e]);
            }
        }
        pf[r] = v;
    }
}

extern __shared__ float smem[];

__global__ void __launch_bounds__(512, 1)
edge_kernel(const float* __restrict__ src,       // (NN, DD)
            const float* __restrict__ add_info,  // (E, 1)
            const int*   __restrict__ nbr_idx,   // (E,)
            const float* __restrict__ W1,        // (259, 128)
            const float* __restrict__ W2,        // (128, 128)
            const float* __restrict__ b2)        // (128,)
{
    float* W1n = smem;                 // KK x HH : rows 0..128 = nbr, 129 = iou, 130/131 = 0
    float* W2s = W1n + KK * HH;        // HH x HH
    float* grp = W2s + HH * HH;
    const int GSZ = 8 * KK + 8 * HH;

    int tid = threadIdx.x;

    for (int i = tid; i < KK * HH; i += 512) {
        int k = i >> 7;
        float v = 0.f;
        if (k < DD) v = W1[i];                        // rows 0..128
        else if (k == DD) v = W1[(2 * DD) * HH + (i & 127)];  // iou row 258
        W1n[i] = v;
    }
    for (int i = tid; i < HH * HH; i += 512) W2s[i] = W2[i];
    __syncthreads();

    const int g  = tid >> 7;
    const int gt = tid & 127;
    float* xs  = grp + g * GSZ;        // 8 x KK
    float* h1s = xs + 8 * KK;          // 8 x HH
    const float bb2 = b2[gt];
    const int barid = g + 1;

    int seg = blockIdx.x * 4 + g;
    const int step = gridDim.x * 4;
    if (seg >= NN) return;

    int s0  = g_segstart[seg];
    int cnt = g_segstart[seg + 1] - s0;
    int eb  = 0;
    float basev = g_base[(size_t)seg * HH + gt];
    float mx = 0.f;                    // h = relu(...) >= 0, cnt >= 1
    float pf[9];
    prefetch_chunk(src, add_info, nbr_idx, s0, cnt < 8 ? cnt : 8, gt, pf);

    while (true) {
        // commit prefetched chunk to smem
#pragma unroll
        for (int r = 0; r < 9; r++) {
            if (r < 8 || gt < 32) xs[gt + (r << 7)] = pf[r];
        }
        asm volatile("bar.sync %0, 128;" :: "r"(barid) : "memory");   // xs ready

        int ne = cnt - eb; if (ne > 8) ne = 8;

        // next chunk coordinates + register prefetch (overlaps compute)
        int nseg = seg, ns0 = s0, ncnt = cnt, neb = eb + 8;
        bool have = true;
        if (neb >= cnt) {
            nseg = seg + step;
            if (nseg < NN) {
                ns0 = g_segstart[nseg];
                ncnt = g_segstart[nseg + 1] - ns0;
                neb = 0;
            } else have = false;
        }
        if (have) {
            int nne = ncnt - neb; if (nne > 8) nne = 8;
            prefetch_chunk(src, add_info, nbr_idx, ns0 + neb, nne, gt, pf);
        }

        // Layer 1: acc[e] = base + sum_k xs[e][k] * W1n[k][t]
        float acc[8];
#pragma unroll
        for (int e = 0; e < 8; e++) acc[e] = basev;
        for (int k = 0; k < KK; k += 4) {
            float w0 = W1n[(k + 0) * HH + gt];
            float w1 = W1n[(k + 1) * HH + gt];
            float w2 = W1n[(k + 2) * HH + gt];
            float w3 = W1n[(k + 3) * HH + gt];
#pragma unroll
            for (int e = 0; e < 8; e++) {
                float4 xv = *reinterpret_cast<const float4*>(&xs[e * KK + k]);
                acc[e] = fmaf(xv.x, w0, acc[e]);
                acc[e] = fmaf(xv.y, w1, acc[e]);
                acc[e] = fmaf(xv.z, w2, acc[e]);
                acc[e] = fmaf(xv.w, w3, acc[e]);
            }
        }
#pragma unroll
        for (int e = 0; e < 8; e++) h1s[e * HH + gt] = fmaxf(acc[e], 0.f);
        asm volatile("bar.sync %0, 128;" :: "r"(barid) : "memory");   // h1 ready

        // Layer 2
        float acc2[8];
#pragma unroll
        for (int e = 0; e < 8; e++) acc2[e] = bb2;
        for (int j = 0; j < HH; j += 4) {
            float w0 = W2s[(j + 0) * HH + gt];
            float w1 = W2s[(j + 1) * HH + gt];
            float w2 = W2s[(j + 2) * HH + gt];
            float w3 = W2s[(j + 3) * HH + gt];
#pragma unroll
            for (int e = 0; e < 8; e++) {
                float4 hv = *reinterpret_cast<const float4*>(&h1s[e * HH + j]);
                acc2[e] = fmaf(hv.x, w0, acc2[e]);
                acc2[e] = fmaf(hv.y, w1, acc2[e]);
                acc2[e] = fmaf(hv.z, w2, acc2[e]);
                acc2[e] = fmaf(hv.w, w3, acc2[e]);
            }
        }
#pragma unroll
        for (int e = 0; e < 8; e++)
            if (e < ne) mx = fmaxf(mx, fmaxf(acc2[e], 0.f));

        if (eb + 8 >= cnt) {
            g_pooled[(size_t)seg * HH + gt] = mx;
            mx = 0.f;
            if (!have) break;
            basev = g_base[(size_t)nseg * HH + gt];
        }
        seg = nseg; s0 = ns0; cnt = ncnt; eb = neb;
    }
}

// ---------------------------------------------------------------------------
// g_interp[n] = src[n] + bo + pooled[n] @ Wo     (Wo: 128 x 129)
// ---------------------------------------------------------------------------
__global__ void __launch_bounds__(256)
wo_kernel(const float* __restrict__ src,
          const float* __restrict__ Wo,
          const float* __restrict__ bo)
{
    extern __shared__ float sm[];
    float* Wos = sm;                 // HH * DD
    float* ps  = Wos + HH * DD;      // 16 * HH
    int tid = threadIdx.x;
    for (int i = tid; i < HH * DD; i += 256) Wos[i] = Wo[i];

    int rb = blockIdx.x * 16;
    __syncthreads();
    for (int i = tid; i < 16 * HH; i += 256) {
        int r = i >> 7;
        ps[i] = g_pooled[(size_t)(rb + r) * HH + (i & 127)];
    }
    __syncthreads();
    for (int i = tid; i < 16 * DD; i += 256) {
        int r = i / DD, c = i - r * DD;
        const float* pr = &ps[r * HH];
        float a0 = 0.f, a1 = 0.f, a2 = 0.f, a3 = 0.f;
#pragma unroll 4
        for (int j = 0; j < HH; j += 4) {
            a0 = fmaf(pr[j + 0], Wos[(j + 0) * DD + c], a0);
            a1 = fmaf(pr[j + 1], Wos[(j + 1) * DD + c], a1);
            a2 = fmaf(pr[j + 2], Wos[(j + 2) * DD + c], a2);
            a3 = fmaf(pr[j + 3], Wos[(j + 3) * DD + c], a3);
        }
        size_t o = (size_t)(rb + r) * DD + c;
        g_interp[o] = src[o] + bo[c] + ((a0 + a1) + (a2 + a3));
    }
}

// ---------------------------------------------------------------------------
// out[n] = relu(g_interp[n] @ fW1 + fb1) @ fW2 + fb2   (129 -> 64 -> 1)
// ---------------------------------------------------------------------------
__global__ void __launch_bounds__(256)
final_kernel(const float* __restrict__ fW1, const float* __restrict__ fb1,
             const float* __restrict__ fW2, const float* __restrict__ fb2,
             float* __restrict__ out)
{
    __shared__ float W1s[DD * 64];
    __shared__ float w2s[64];
    __shared__ float b1s[64];
    int tid = threadIdx.x;
    for (int i = tid; i < DD * 64; i += 256) W1s[i] = fW1[i];
    if (tid < 64) { w2s[tid] = fW2[tid]; b1s[tid] = fb1[tid]; }
    __syncthreads();
    float fb2v = fb2[0];
    int warp = tid >> 5, lane = tid & 31;
    int n = blockIdx.x * 8 + warp;
    if (n >= NN) return;
    const float* row = g_interp + (size_t)n * DD;
    float h0 = b1s[lane], h1 = b1s[lane + 32];
    for (int k = 0; k < DD; k++) {
        float x = row[k];
        h0 = fmaf(x, W1s[k * 64 + lane],      h0);
        h1 = fmaf(x, W1s[k * 64 + lane + 32], h1);
    }
    float v = fmaxf(h0, 0.f) * w2s[lane] + fmaxf(h1, 0.f) * w2s[lane + 32];
#pragma unroll
    for (int off = 16; off; off >>= 1)
        v += __shfl_down_sync(0xffffffffu, v, off);
    if (lane == 0) out[n] = v + fb2v;
}

// ---------------------------------------------------------------------------
extern "C" void kernel_launch(void* const* d_in, const int* in_sizes, int n_in,
                              void* d_out, int out_size)
{
    (void)in_sizes; (void)n_in; (void)out_size;

    const float* interp_in = (const float*)d_in[0];
    const float* add_info  = (const float*)d_in[1];
    const int*   sizes     = (const int*)d_in[2];
    const int*   nbr       = (const int*)d_in[3];
    const float* b0W1 = (const float*)d_in[5];
    const float* b0b1 = (const float*)d_in[6];
    const float* b0W2 = (const float*)d_in[7];
    const float* b0b2 = (const float*)d_in[8];
    const float* b0Wo = (const float*)d_in[9];
    const float* b0bo = (const float*)d_in[10];
    const float* b1W1 = (const float*)d_in[11];
    const float* b1b1 = (const float*)d_in[12];
    const float* b1W2 = (const float*)d_in[13];
    const float* b1b2 = (const float*)d_in[14];
    const float* b1Wo = (const float*)d_in[15];
    const float* b1bo = (const float*)d_in[16];
    const float* fW1  = (const float*)d_in[17];
    const float* fb1  = (const float*)d_in[18];
    const float* fW2  = (const float*)d_in[19];
    const float* fb2  = (const float*)d_in[20];
    float* out = (float*)d_out;

    float* ginterp = nullptr;
    cudaGetSymbolAddress((void**)&ginterp, g_interp);

    int nsm = 148;
    cudaDeviceGetAttribute(&nsm, cudaDevAttrMultiProcessorCount, 0);

    size_t edge_smem = (size_t)(KK * HH + HH * HH +
                                4 * (8 * KK + 8 * HH)) * sizeof(float);
    cudaFuncSetAttribute(edge_kernel,
                         cudaFuncAttributeMaxDynamicSharedMemorySize,
                         (int)edge_smem);
    size_t base_smem = (size_t)(DD * HH + 16 * DD) * sizeof(float);
    cudaFuncSetAttribute(base_kernel,
                         cudaFuncAttributeMaxDynamicSharedMemorySize,
                         (int)base_smem);
    size_t wo_smem = (size_t)(HH * DD + 16 * HH) * sizeof(float);
    cudaFuncSetAttribute(wo_kernel,
                         cudaFuncAttributeMaxDynamicSharedMemorySize,
                         (int)wo_smem);

    scan_kernel<<<1, 1024>>>(sizes);

    // block 0
    base_kernel<<<NN / 16, 256, base_smem>>>(interp_in, b0W1, b0b1);
    edge_kernel<<<nsm, 512, edge_smem>>>(interp_in, add_info, nbr,
                                         b0W1, b0W2, b0b2);
    wo_kernel<<<NN / 16, 256, wo_smem>>>(interp_in, b0Wo, b0bo);

    // block 1
    base_kernel<<<NN / 16, 256, base_smem>>>(ginterp, b1W1, b1b1);
    edge_kernel<<<nsm, 512, edge_smem>>>(ginterp, add_info, nbr,
                                         b1W1, b1W2, b1b2);
    wo_kernel<<<NN / 16, 256, wo_smem>>>(ginterp, b1Wo, b1bo);

    // final scorer
    final_kernel<<<NN / 8, 256>>>(fW1, fb1, fW2, fb2, out);
}

// round 4
// speedup vs baseline: 3.5274x; 2.9538x over previous
#include <cuda_runtime.h>
#include <cuda_bf16.h>
#include <cstdint>
#include <cstddef>

#define NN 15872
#define DD 129
#define HH 128
#define EE 253952
#define NTILES 1984   // EE / 128 exactly

static __device__ float g_interp[NN * DD];
static __device__ float g_pooled[NN * HH];
static __device__ float g_base[NN * HH];

// ---------------------------------------------------------------------------
static __device__ __forceinline__ uint32_t smem_u32(const void* p) {
    uint32_t a;
    asm("{ .reg .u64 t; cvta.to.shared.u64 t, %1; cvt.u32.u64 %0, t; }"
        : "=r"(a) : "l"(p));
    return a;
}

// XOR-swizzled byte offset inside a 128x128 bf16 tile (256B rows, 16B units):
// unit = k>>3 XOR (row&7)  -> conflict-free ldmatrix & stores
#define SWZ(row, k) ((((uint32_t)(row)) << 8) + \
                     (((((uint32_t)(k) >> 3) ^ ((uint32_t)(row) & 7u))) << 4) + \
                     ((((uint32_t)(k)) & 7u) << 1))

#define LDMATRIX_X4(r0, r1, r2, r3, addr) \
    asm volatile("ldmatrix.sync.aligned.m8n8.x4.shared.b16 {%0,%1,%2,%3}, [%4];" \
                 : "=r"(r0), "=r"(r1), "=r"(r2), "=r"(r3) : "r"(addr))

#define MMA16816(d, a, b0, b1) \
    asm volatile("mma.sync.aligned.m16n8k16.row.col.f32.bf16.bf16.f32 " \
                 "{%0,%1,%2,%3}, {%4,%5,%6,%7}, {%8,%9}, {%0,%1,%2,%3};" \
                 : "+f"((d)[0]), "+f"((d)[1]), "+f"((d)[2]), "+f"((d)[3]) \
                 : "r"((a)[0]), "r"((a)[1]), "r"((a)[2]), "r"((a)[3]), \
                   "r"(b0), "r"(b1))

static __device__ __forceinline__ void split2(float a, float b,
                                              uint32_t& hi, uint32_t& lo) {
    __nv_bfloat16 ah = __float2bfloat16_rn(a);
    __nv_bfloat16 bh = __float2bfloat16_rn(b);
    float ar = a - __bfloat162float(ah);
    float br = b - __bfloat162float(bh);
    __nv_bfloat162 h; h.x = ah; h.y = bh;
    __nv_bfloat162 l = __floats2bfloat162_rn(ar, br);
    hi = *reinterpret_cast<uint32_t*>(&h);
    lo = *reinterpret_cast<uint32_t*>(&l);
}

// ------------------------------- SMEM map (bytes) ---------------------------
#define OFF_AH   0u
#define OFF_AL   32768u
#define OFF_W1H  65536u
#define OFF_W1L  98304u
#define OFF_W2H  131072u
#define OFF_W2L  163840u
#define OFF_SELF 196608u   // 128 int
#define OFF_C128 197120u   // 128 float
#define OFF_IOU  197632u
#define OFF_W128 198144u
#define OFF_W258 198656u
#define OFF_B2   199168u
#define SMEM_EDGE 199680u

// ---------------------------------------------------------------------------
// base[n][t] = b1[t] + sum_j src[n][j] * W1[129+j][t]   (fp32 full precision)
// ---------------------------------------------------------------------------
__global__ void __launch_bounds__(256)
base_kernel(const float* __restrict__ src,
            const float* __restrict__ W1,
            const float* __restrict__ b1)
{
    extern __shared__ float sm[];
    float* Wm   = sm;
    float* xsrc = Wm + DD * HH;
    int tid = threadIdx.x;
    for (int i = tid; i < DD * HH; i += 256) Wm[i] = W1[DD * HH + i];
    int rb = blockIdx.x * 16;
    for (int i = tid; i < 16 * DD; i += 256) {
        int r = i / DD, c = i - r * DD;
        xsrc[i] = src[(size_t)(rb + r) * DD + c];
    }
    __syncthreads();
    int t = tid & 127, p = tid >> 7;
    float acc[8];
    float bb = b1[t];
#pragma unroll
    for (int i = 0; i < 8; i++) acc[i] = bb;
    for (int j = 0; j < DD; j++) {
        float w = Wm[j * HH + t];
#pragma unroll
        for (int i = 0; i < 8; i++)
            acc[i] = fmaf(xsrc[(p + 2 * i) * DD + j], w, acc[i]);
    }
#pragma unroll
    for (int i = 0; i < 8; i++)
        g_base[(size_t)(rb + p + 2 * i) * HH + t] = acc[i];
}

// ---------------------------------------------------------------------------
// One 128x128x128 bf16 GEMM pass: C += A(offA) @ W(offW)^T, warp tile 32x64.
// ---------------------------------------------------------------------------
static __device__ __forceinline__ void gemm128(uint32_t smb, uint32_t offA,
                                               uint32_t offW,
                                               float (&acc)[2][8][4],
                                               int warp_m, int warp_n, int lid)
{
    const int mi  = lid >> 3;
    const int l7  = lid & 7;
    const int arow_d = l7 + ((mi & 1) << 3);
    const int akk_d  = (mi >> 1) << 3;
    const int brow_d = l7 + ((mi >> 1) << 3);
    const int bkk_d  = (mi & 1) << 3;

#pragma unroll
    for (int ks = 0; ks < 8; ks++) {
        const int k0 = ks * 16;
        uint32_t a[2][4];
#pragma unroll
        for (int mt = 0; mt < 2; mt++) {
            uint32_t ad = smb + offA +
                SWZ(warp_m * 32 + mt * 16 + arow_d, k0 + akk_d);
            LDMATRIX_X4(a[mt][0], a[mt][1], a[mt][2], a[mt][3], ad);
        }
#pragma unroll
        for (int q = 0; q < 4; q++) {
            uint32_t bd = smb + offW +
                SWZ(warp_n * 64 + q * 16 + brow_d, k0 + bkk_d);
            uint32_t b0, b1, b2, b3;
            LDMATRIX_X4(b0, b1, b2, b3, bd);
#pragma unroll
            for (int mt = 0; mt < 2; mt++) {
                MMA16816(acc[mt][2 * q + 0], a[mt], b0, b1);
                MMA16816(acc[mt][2 * q + 1], a[mt], b2, b3);
            }
        }
    }
}

// ---------------------------------------------------------------------------
// Tensor-core (HMMA) edge kernel.
// ---------------------------------------------------------------------------
__global__ void __launch_bounds__(256, 1)
edge_tc_kernel(const float* __restrict__ src,
               const float* __restrict__ add_info,
               const int*   __restrict__ nbr_idx,
               const int*   __restrict__ self_idx,
               const float* __restrict__ W1,
               const float* __restrict__ W2,
               const float* __restrict__ b2)
{
    extern __shared__ char sm8[];
    const uint32_t smb = smem_u32(sm8);
    const int tid = threadIdx.x;
    const int wid = tid >> 5, lid = tid & 31;
    const int warp_m = wid >> 1;        // 0..3
    const int warp_n = wid & 1;         // 0..1

    // ---- stage weights: [h][k] hi/lo split, swizzled ----
    for (int idx = tid; idx < HH * HH; idx += 256) {
        int h = idx & 127, k = idx >> 7;           // read W[k*128+h] coalesced
        float w1 = W1[idx];
        float w2 = W2[idx];
        uint32_t a = SWZ(h, k);                    // 2-byte slot
        __nv_bfloat16 w1h = __float2bfloat16_rn(w1);
        __nv_bfloat16 w2h = __float2bfloat16_rn(w2);
        __nv_bfloat16 w1l = __float2bfloat16_rn(w1 - __bfloat162float(w1h));
        __nv_bfloat16 w2l = __float2bfloat16_rn(w2 - __bfloat162float(w2h));
        *reinterpret_cast<__nv_bfloat16*>(sm8 + OFF_W1H + a) = w1h;
        *reinterpret_cast<__nv_bfloat16*>(sm8 + OFF_W1L + a) = w1l;
        *reinterpret_cast<__nv_bfloat16*>(sm8 + OFF_W2H + a) = w2h;
        *reinterpret_cast<__nv_bfloat16*>(sm8 + OFF_W2L + a) = w2l;
    }
    if (tid < 128) {
        ((float*)(sm8 + OFF_W128))[tid] = W1[128 * HH + tid];
        ((float*)(sm8 + OFF_W258))[tid] = W1[258 * HH + tid];
        ((float*)(sm8 + OFF_B2))[tid]   = b2[tid];
    }
    __syncthreads();

    const float* w128s = (const float*)(sm8 + OFF_W128);
    const float* w258s = (const float*)(sm8 + OFF_W258);
    const float* b2s   = (const float*)(sm8 + OFF_B2);
    const int*   selfs = (const int*)(sm8 + OFF_SELF);
    const float* c128s = (const float*)(sm8 + OFF_C128);
    const float* ious  = (const float*)(sm8 + OFF_IOU);

    for (int tile = blockIdx.x; tile < NTILES; tile += gridDim.x) {
        const int t0 = tile * 128;
        __syncthreads();   // previous tile fully consumed

        // ---- gather A: 128 edges x 128 feats, hi/lo split ----
        for (int r = wid; r < 128; r += 8) {
            int nb = __ldg(&nbr_idx[t0 + r]);
            const float* row = src + (size_t)nb * DD;
            int c0 = lid * 4;
            float x0 = __ldg(row + c0 + 0);
            float x1 = __ldg(row + c0 + 1);
            float x2 = __ldg(row + c0 + 2);
            float x3 = __ldg(row + c0 + 3);
            uint2 hv, lv;
            split2(x0, x1, hv.x, lv.x);
            split2(x2, x3, hv.y, lv.y);
            uint32_t a = SWZ(r, c0);               // 8B aligned
            *reinterpret_cast<uint2*>(sm8 + OFF_AH + a) = hv;
            *reinterpret_cast<uint2*>(sm8 + OFF_AL + a) = lv;
            if (lid == 0) {
                ((int*)(sm8 + OFF_SELF))[r]   = __ldg(&self_idx[t0 + r]);
                ((float*)(sm8 + OFF_C128))[r] = __ldg(row + 128);
                ((float*)(sm8 + OFF_IOU))[r]  = __ldg(&add_info[t0 + r]);
            }
        }
        __syncthreads();

        // ---- layer-1 GEMM (3 bf16 passes) ----
        float acc[2][8][4];
#pragma unroll
        for (int i = 0; i < 2; i++)
#pragma unroll
            for (int j = 0; j < 8; j++)
#pragma unroll
                for (int c = 0; c < 4; c++) acc[i][j][c] = 0.f;

        {
            const uint32_t pa[3] = {OFF_AH, OFF_AH, OFF_AL};
            const uint32_t pw[3] = {OFF_W1H, OFF_W1L, OFF_W1H};
#pragma unroll 1
            for (int p = 0; p < 3; p++)
                gemm128(smb, pa[p], pw[p], acc, warp_m, warp_n, lid);
        }
        __syncthreads();   // everyone done reading A before H overwrites it

        // ---- epilogue 1: finish layer-1, relu, restage H (hi/lo) ----
#pragma unroll
        for (int mt = 0; mt < 2; mt++) {
            int row0 = warp_m * 32 + mt * 16 + (lid >> 2);
            int row1 = row0 + 8;
            int s0 = selfs[row0], s1 = selfs[row1];
            float cA0 = c128s[row0], cA1 = c128s[row1];
            float iv0 = ious[row0],  iv1 = ious[row1];
            const float* bp0 = g_base + (size_t)s0 * HH;
            const float* bp1 = g_base + (size_t)s1 * HH;
#pragma unroll
            for (int nt = 0; nt < 8; nt++) {
                int col = warp_n * 64 + nt * 8 + ((lid & 3) << 1);
                float2 B0 = *reinterpret_cast<const float2*>(bp0 + col);
                float2 B1 = *reinterpret_cast<const float2*>(bp1 + col);
                float2 WA = *reinterpret_cast<const float2*>(w128s + col);
                float2 WI = *reinterpret_cast<const float2*>(w258s + col);
                float h00 = fmaxf(acc[mt][nt][0] + B0.x + cA0 * WA.x + iv0 * WI.x, 0.f);
                float h01 = fmaxf(acc[mt][nt][1] + B0.y + cA0 * WA.y + iv0 * WI.y, 0.f);
                float h10 = fmaxf(acc[mt][nt][2] + B1.x + cA1 * WA.x + iv1 * WI.x, 0.f);
                float h11 = fmaxf(acc[mt][nt][3] + B1.y + cA1 * WA.y + iv1 * WI.y, 0.f);
                uint32_t hi, lo;
                split2(h00, h01, hi, lo);
                uint32_t a0 = SWZ(row0, col);
                *reinterpret_cast<uint32_t*>(sm8 + OFF_AH + a0) = hi;
                *reinterpret_cast<uint32_t*>(sm8 + OFF_AL + a0) = lo;
                split2(h10, h11, hi, lo);
                uint32_t a1 = SWZ(row1, col);
                *reinterpret_cast<uint32_t*>(sm8 + OFF_AH + a1) = hi;
                *reinterpret_cast<uint32_t*>(sm8 + OFF_AL + a1) = lo;
            }
        }
        __syncthreads();

        // ---- layer-2 GEMM (3 bf16 passes) ----
#pragma unroll
        for (int i = 0; i < 2; i++)
#pragma unroll
            for (int j = 0; j < 8; j++)
#pragma unroll
                for (int c = 0; c < 4; c++) acc[i][j][c] = 0.f;
        {
            const uint32_t pa[3] = {OFF_AH, OFF_AH, OFF_AL};
            const uint32_t pw[3] = {OFF_W2H, OFF_W2L, OFF_W2H};
#pragma unroll 1
            for (int p = 0; p < 3; p++)
                gemm128(smb, pa[p], pw[p], acc, warp_m, warp_n, lid);
        }

        // ---- epilogue 2: bias + relu + segment atomicMax ----
#pragma unroll
        for (int mt = 0; mt < 2; mt++) {
            int row0 = warp_m * 32 + mt * 16 + (lid >> 2);
            int row1 = row0 + 8;
            int s0 = selfs[row0], s1 = selfs[row1];
            int* gp0 = reinterpret_cast<int*>(g_pooled) + (size_t)s0 * HH;
            int* gp1 = reinterpret_cast<int*>(g_pooled) + (size_t)s1 * HH;
#pragma unroll
            for (int nt = 0; nt < 8; nt++) {
                int col = warp_n * 64 + nt * 8 + ((lid & 3) << 1);
                float2 BB = *reinterpret_cast<const float2*>(b2s + col);
                float v00 = fmaxf(acc[mt][nt][0] + BB.x, 0.f);
                float v01 = fmaxf(acc[mt][nt][1] + BB.y, 0.f);
                float v10 = fmaxf(acc[mt][nt][2] + BB.x, 0.f);
                float v11 = fmaxf(acc[mt][nt][3] + BB.y, 0.f);
                atomicMax(gp0 + col,     __float_as_int(v00));
                atomicMax(gp0 + col + 1, __float_as_int(v01));
                atomicMax(gp1 + col,     __float_as_int(v10));
                atomicMax(gp1 + col + 1, __float_as_int(v11));
            }
        }
    }
}

// ---------------------------------------------------------------------------
// g_interp[n] = src[n] + bo + pooled[n] @ Wo   (64 rows/block, 8x4 reg tiles)
// ---------------------------------------------------------------------------
__global__ void __launch_bounds__(288)
wo_kernel(const float* __restrict__ src,
          const float* __restrict__ Wo,
          const float* __restrict__ bo)
{
    extern __shared__ float sm[];
    float* Wos = sm;                 // 128 x 132 (zero padded)
    float* ps  = Wos + 128 * 132;    // 64 x 128
    int tid = threadIdx.x;
    for (int i = tid; i < 128 * 132; i += 288) {
        int j = i / 132, c = i - j * 132;
        Wos[i] = (c < DD) ? Wo[j * DD + c] : 0.f;
    }
    int rb = blockIdx.x * 64;
    for (int i = tid; i < 64 * 128; i += 288) {
        int r = i >> 7;
        ps[i] = g_pooled[(size_t)(rb + r) * HH + (i & 127)];
    }
    __syncthreads();
    int rg = tid / 36, cg = tid - rg * 36;
    if (cg >= 33) return;
    int c0 = cg * 4, r0 = rg * 8;
    float acc[8][4];
#pragma unroll
    for (int r = 0; r < 8; r++)
#pragma unroll
        for (int c = 0; c < 4; c++) acc[r][c] = 0.f;
    for (int j = 0; j < 128; j++) {
        float4 w = *reinterpret_cast<const float4*>(&Wos[j * 132 + c0]);
#pragma unroll
        for (int r = 0; r < 8; r++) {
            float p = ps[(r0 + r) * 128 + j];
            acc[r][0] = fmaf(p, w.x, acc[r][0]);
            acc[r][1] = fmaf(p, w.y, acc[r][1]);
            acc[r][2] = fmaf(p, w.z, acc[r][2]);
            acc[r][3] = fmaf(p, w.w, acc[r][3]);
        }
    }
#pragma unroll
    for (int r = 0; r < 8; r++)
#pragma unroll
        for (int c = 0; c < 4; c++) {
            int col = c0 + c;
            if (col < DD) {
                size_t o = (size_t)(rb + r0 + r) * DD + col;
                g_interp[o] = src[o] + bo[col] + acc[r][c];
            }
        }
}

// ---------------------------------------------------------------------------
// out[n] = relu(g_interp[n] @ fW1 + fb1) @ fW2 + fb2   (129 -> 64 -> 1)
// ---------------------------------------------------------------------------
__global__ void __launch_bounds__(256)
final_kernel(const float* __restrict__ fW1, const float* __restrict__ fb1,
             const float* __restrict__ fW2, const float* __restrict__ fb2,
             float* __restrict__ out)
{
    __shared__ float W1s[DD * 64];
    __shared__ float w2s[64];
    __shared__ float b1s[64];
    int tid = threadIdx.x;
    for (int i = tid; i < DD * 64; i += 256) W1s[i] = fW1[i];
    if (tid < 64) { w2s[tid] = fW2[tid]; b1s[tid] = fb1[tid]; }
    __syncthreads();
    float fb2v = fb2[0];
    int warp = tid >> 5, lane = tid & 31;
    int n = blockIdx.x * 8 + warp;
    if (n >= NN) return;
    const float* row = g_interp + (size_t)n * DD;
    float h0 = b1s[lane], h1 = b1s[lane + 32];
    for (int k = 0; k < DD; k++) {
        float x = row[k];
        h0 = fmaf(x, W1s[k * 64 + lane],      h0);
        h1 = fmaf(x, W1s[k * 64 + lane + 32], h1);
    }
    float v = fmaxf(h0, 0.f) * w2s[lane] + fmaxf(h1, 0.f) * w2s[lane + 32];
#pragma unroll
    for (int off = 16; off; off >>= 1)
        v += __shfl_down_sync(0xffffffffu, v, off);
    if (lane == 0) out[n] = v + fb2v;
}

// ---------------------------------------------------------------------------
extern "C" void kernel_launch(void* const* d_in, const int* in_sizes, int n_in,
                              void* d_out, int out_size)
{
    (void)in_sizes; (void)n_in; (void)out_size;

    const float* interp_in = (const float*)d_in[0];
    const float* add_info  = (const float*)d_in[1];
    const int*   nbr       = (const int*)d_in[3];
    const int*   self      = (const int*)d_in[4];
    const float* b0W1 = (const float*)d_in[5];
    const float* b0b1 = (const float*)d_in[6];
    const float* b0W2 = (const float*)d_in[7];
    const float* b0b2 = (const float*)d_in[8];
    const float* b0Wo = (const float*)d_in[9];
    const float* b0bo = (const float*)d_in[10];
    const float* b1W1 = (const float*)d_in[11];
    const float* b1b1 = (const float*)d_in[12];
    const float* b1W2 = (const float*)d_in[13];
    const float* b1b2 = (const float*)d_in[14];
    const float* b1Wo = (const float*)d_in[15];
    const float* b1bo = (const float*)d_in[16];
    const float* fW1  = (const float*)d_in[17];
    const float* fb1  = (const float*)d_in[18];
    const float* fW2  = (const float*)d_in[19];
    const float* fb2  = (const float*)d_in[20];
    float* out = (float*)d_out;

    float* ginterp = nullptr;
    cudaGetSymbolAddress((void**)&ginterp, g_interp);
    float* gpooled = nullptr;
    cudaGetSymbolAddress((void**)&gpooled, g_pooled);

    int nsm = 148;
    cudaDeviceGetAttribute(&nsm, cudaDevAttrMultiProcessorCount, 0);

    cudaFuncSetAttribute(edge_tc_kernel,
                         cudaFuncAttributeMaxDynamicSharedMemorySize,
                         (int)SMEM_EDGE);
    size_t base_smem = (size_t)(DD * HH + 16 * DD) * sizeof(float);
    cudaFuncSetAttribute(base_kernel,
                         cudaFuncAttributeMaxDynamicSharedMemorySize,
                         (int)base_smem);
    size_t wo_smem = (size_t)(128 * 132 + 64 * 128) * sizeof(float);
    cudaFuncSetAttribute(wo_kernel,
                         cudaFuncAttributeMaxDynamicSharedMemorySize,
                         (int)wo_smem);

    const size_t pooled_bytes = (size_t)NN * HH * sizeof(float);

    // block 0
    cudaMemsetAsync(gpooled, 0, pooled_bytes);
    base_kernel<<<NN / 16, 256, base_smem>>>(interp_in, b0W1, b0b1);
    edge_tc_kernel<<<nsm, 256, SMEM_EDGE>>>(interp_in, add_info, nbr, self,
                                            b0W1, b0W2, b0b2);
    wo_kernel<<<NN / 64, 288, wo_smem>>>(interp_in, b0Wo, b0bo);

    // block 1
    cudaMemsetAsync(gpooled, 0, pooled_bytes);
    base_kernel<<<NN / 16, 256, base_smem>>>(ginterp, b1W1, b1b1);
    edge_tc_kernel<<<nsm, 256, SMEM_EDGE>>>(ginterp, add_info, nbr, self,
                                            b1W1, b1W2, b1b2);
    wo_kernel<<<NN / 64, 288, wo_smem>>>(ginterp, b1Wo, b1bo);

    // final scorer
    final_kernel<<<NN / 8, 256>>>(fW1, fb1, fW2, fb2, out);
}

// round 5
// speedup vs baseline: 3.8871x; 1.1020x over previous
#include <cuda_runtime.h>
#include <cuda_bf16.h>
#include <cstdint>
#include <cstddef>

#define NN 15872
#define DD 129
#define HH 128
#define EE 253952
#define NTILES 1984   // EE / 128 exactly
#define NODTILES 124  // NN / 128 exactly

static __device__ float g_interp[NN * DD];
static __device__ float g_pooled[NN * HH];
static __device__ float g_base[NN * HH];

// ---------------------------------------------------------------------------
static __device__ __forceinline__ uint32_t smem_u32(const void* p) {
    uint32_t a;
    asm("{ .reg .u64 t; cvta.to.shared.u64 t, %1; cvt.u32.u64 %0, t; }"
        : "=r"(a) : "l"(p));
    return a;
}

// XOR-swizzled byte offset inside a 128x128 bf16 tile (256B rows, 16B units)
#define SWZ(row, k) ((((uint32_t)(row)) << 8) + \
                     (((((uint32_t)(k) >> 3) ^ ((uint32_t)(row) & 7u))) << 4) + \
                     ((((uint32_t)(k)) & 7u) << 1))

// fp32 V tile word offset (128x128 floats), 16B-unit xor swizzle:
// conflict-free row-wise warp reads; <=2-way on fragment stores
#define VOFF(r, c) ((((uint32_t)(r)) << 7) + \
                    (((((uint32_t)(c) >> 2) ^ ((uint32_t)(r) & 7u)) << 2) | \
                     ((uint32_t)(c) & 3u)))

#define LDMATRIX_X4(r0, r1, r2, r3, addr) \
    asm volatile("ldmatrix.sync.aligned.m8n8.x4.shared.b16 {%0,%1,%2,%3}, [%4];" \
                 : "=r"(r0), "=r"(r1), "=r"(r2), "=r"(r3) : "r"(addr))

#define MMA16816(d, a, b0, b1) \
    asm volatile("mma.sync.aligned.m16n8k16.row.col.f32.bf16.bf16.f32 " \
                 "{%0,%1,%2,%3}, {%4,%5,%6,%7}, {%8,%9}, {%0,%1,%2,%3};" \
                 : "+f"((d)[0]), "+f"((d)[1]), "+f"((d)[2]), "+f"((d)[3]) \
                 : "r"((a)[0]), "r"((a)[1]), "r"((a)[2]), "r"((a)[3]), \
                   "r"(b0), "r"(b1))

static __device__ __forceinline__ void split2(float a, float b,
                                              uint32_t& hi, uint32_t& lo) {
    __nv_bfloat16 ah = __float2bfloat16_rn(a);
    __nv_bfloat16 bh = __float2bfloat16_rn(b);
    float ar = a - __bfloat162float(ah);
    float br = b - __bfloat162float(bh);
    __nv_bfloat162 h; h.x = ah; h.y = bh;
    __nv_bfloat162 l = __floats2bfloat162_rn(ar, br);
    hi = *reinterpret_cast<uint32_t*>(&h);
    lo = *reinterpret_cast<uint32_t*>(&l);
}

// ------------------------------- SMEM maps ----------------------------------
// edge kernel
#define OFF_AH   0u
#define OFF_AL   32768u
#define OFF_W1H  65536u
#define OFF_W1L  98304u
#define OFF_W2H  131072u
#define OFF_W2L  163840u
#define OFF_SELF 196608u
#define OFF_C128 197120u
#define OFF_IOU  197632u
#define OFF_W128 198144u
#define OFF_W258 198656u
#define OFF_B2   199168u
#define SMEM_EDGE 199680u
// dense kernels (base/wo)
#define DOFF_AH  0u
#define DOFF_AL  32768u
#define DOFF_WH  65536u
#define DOFF_WL  98304u
#define DOFF_X1  131072u   // 128 floats
#define DOFF_X2  131584u   // 128 floats
#define DOFF_X3  132096u   // up to 192 floats
#define SMEM_DENSE 132864u

// ---------------------------------------------------------------------------
// One 128x128x128 bf16 GEMM pass: C += A(offA) @ W(offW)^T, warp tile 32x64.
// ---------------------------------------------------------------------------
static __device__ __forceinline__ void gemm128(uint32_t smb, uint32_t offA,
                                               uint32_t offW,
                                               float (&acc)[2][8][4],
                                               int warp_m, int warp_n, int lid)
{
    const int mi  = lid >> 3;
    const int l7  = lid & 7;
    const int arow_d = l7 + ((mi & 1) << 3);
    const int akk_d  = (mi >> 1) << 3;
    const int brow_d = l7 + ((mi >> 1) << 3);
    const int bkk_d  = (mi & 1) << 3;

#pragma unroll
    for (int ks = 0; ks < 8; ks++) {
        const int k0 = ks * 16;
        uint32_t a[2][4];
#pragma unroll
        for (int mt = 0; mt < 2; mt++) {
            uint32_t ad = smb + offA +
                SWZ(warp_m * 32 + mt * 16 + arow_d, k0 + akk_d);
            LDMATRIX_X4(a[mt][0], a[mt][1], a[mt][2], a[mt][3], ad);
        }
#pragma unroll
        for (int q = 0; q < 4; q++) {
            uint32_t bd = smb + offW +
                SWZ(warp_n * 64 + q * 16 + brow_d, k0 + bkk_d);
            uint32_t b0, b1, b2, b3;
            LDMATRIX_X4(b0, b1, b2, b3, bd);
#pragma unroll
            for (int mt = 0; mt < 2; mt++) {
                MMA16816(acc[mt][2 * q + 0], a[mt], b0, b1);
                MMA16816(acc[mt][2 * q + 1], a[mt], b2, b3);
            }
        }
    }
}

// ---------------------------------------------------------------------------
// HMMA base kernel: base[n][t] = b1[t] + sum_{j=0..128} src[n][129+... ] ...
//   GEMM over main feats j=0..127 (W1 rows 129..256); j=128 (row 257) + b1 in
//   the epilogue (fp32).
// ---------------------------------------------------------------------------
__global__ void __launch_bounds__(256, 1)
base_hmma(const float* __restrict__ src,
          const float* __restrict__ W1,
          const float* __restrict__ b1)
{
    extern __shared__ char sm8[];
    const uint32_t smb = smem_u32(sm8);
    const int tid = threadIdx.x;
    const int wid = tid >> 5, lid = tid & 31;
    const int warp_m = wid >> 1, warp_n = wid & 1;

    for (int idx = tid; idx < HH * HH; idx += 256) {
        int j = idx >> 7, t = idx & 127;
        float w = W1[(129 + j) * HH + t];
        uint32_t hi, lo;
        __nv_bfloat16 wh = __float2bfloat16_rn(w);
        __nv_bfloat16 wl = __float2bfloat16_rn(w - __bfloat162float(wh));
        hi = (uint32_t)*reinterpret_cast<uint16_t*>(&wh);
        lo = (uint32_t)*reinterpret_cast<uint16_t*>(&wl);
        uint32_t a = SWZ(t, j);
        *reinterpret_cast<uint16_t*>(sm8 + DOFF_WH + a) = (uint16_t)hi;
        *reinterpret_cast<uint16_t*>(sm8 + DOFF_WL + a) = (uint16_t)lo;
    }
    if (tid < 128) {
        ((float*)(sm8 + DOFF_X1))[tid] = W1[257 * HH + tid];   // w for main[128]
        ((float*)(sm8 + DOFF_X2))[tid] = b1[tid];
    }
    const int rb = blockIdx.x * 128;
    for (int r = wid; r < 128; r += 8) {
        const float* row = src + (size_t)(rb + r) * DD;
        int c0 = lid * 4;
        float x0 = __ldg(row + c0 + 0), x1 = __ldg(row + c0 + 1);
        float x2 = __ldg(row + c0 + 2), x3 = __ldg(row + c0 + 3);
        uint2 hv, lv;
        split2(x0, x1, hv.x, lv.x);
        split2(x2, x3, hv.y, lv.y);
        uint32_t a = SWZ(r, c0);
        *reinterpret_cast<uint2*>(sm8 + DOFF_AH + a) = hv;
        *reinterpret_cast<uint2*>(sm8 + DOFF_AL + a) = lv;
        if (lid == 0) ((float*)(sm8 + DOFF_X3))[r] = __ldg(row + 128);
    }
    __syncthreads();

    float acc[2][8][4];
#pragma unroll
    for (int i = 0; i < 2; i++)
#pragma unroll
        for (int j = 0; j < 8; j++)
#pragma unroll
            for (int c = 0; c < 4; c++) acc[i][j][c] = 0.f;
    {
        const uint32_t pa[3] = {DOFF_AH, DOFF_AH, DOFF_AL};
        const uint32_t pw[3] = {DOFF_WH, DOFF_WL, DOFF_WH};
#pragma unroll 1
        for (int p = 0; p < 3; p++)
            gemm128(smb, pa[p], pw[p], acc, warp_m, warp_n, lid);
    }

    const float* w7 = (const float*)(sm8 + DOFF_X1);
    const float* bb = (const float*)(sm8 + DOFF_X2);
    const float* c1 = (const float*)(sm8 + DOFF_X3);
#pragma unroll
    for (int mt = 0; mt < 2; mt++) {
        int row0 = warp_m * 32 + mt * 16 + (lid >> 2);
        int row1 = row0 + 8;
        float cv0 = c1[row0], cv1 = c1[row1];
#pragma unroll
        for (int nt = 0; nt < 8; nt++) {
            int col = warp_n * 64 + nt * 8 + ((lid & 3) << 1);
            float2 W7 = *reinterpret_cast<const float2*>(w7 + col);
            float2 BB = *reinterpret_cast<const float2*>(bb + col);
            float2 o0, o1;
            o0.x = acc[mt][nt][0] + BB.x + cv0 * W7.x;
            o0.y = acc[mt][nt][1] + BB.y + cv0 * W7.y;
            o1.x = acc[mt][nt][2] + BB.x + cv1 * W7.x;
            o1.y = acc[mt][nt][3] + BB.y + cv1 * W7.y;
            *reinterpret_cast<float2*>(g_base + (size_t)(rb + row0) * HH + col) = o0;
            *reinterpret_cast<float2*>(g_base + (size_t)(rb + row1) * HH + col) = o1;
        }
    }
}

// ---------------------------------------------------------------------------
// HMMA wo kernel: g_interp[n][c] = src[n][c] + bo[c] + pooled[n] @ Wo[:,c]
//   GEMM over cols 0..127; col 128 handled SIMT in the epilogue.
// ---------------------------------------------------------------------------
__global__ void __launch_bounds__(256, 1)
wo_hmma(const float* __restrict__ src,
        const float* __restrict__ Wo,
        const float* __restrict__ bo)
{
    extern __shared__ char sm8[];
    const uint32_t smb = smem_u32(sm8);
    const int tid = threadIdx.x;
    const int wid = tid >> 5, lid = tid & 31;
    const int warp_m = wid >> 1, warp_n = wid & 1;

    for (int idx = tid; idx < HH * HH; idx += 256) {
        int j = idx >> 7, c = idx & 127;
        float w = Wo[j * DD + c];
        __nv_bfloat16 wh = __float2bfloat16_rn(w);
        __nv_bfloat16 wl = __float2bfloat16_rn(w - __bfloat162float(wh));
        uint32_t a = SWZ(c, j);
        *reinterpret_cast<__nv_bfloat16*>(sm8 + DOFF_WH + a) = wh;
        *reinterpret_cast<__nv_bfloat16*>(sm8 + DOFF_WL + a) = wl;
    }
    if (tid < 128) ((float*)(sm8 + DOFF_X1))[tid] = Wo[tid * DD + 128];
    for (int i = tid; i < DD; i += 256) ((float*)(sm8 + DOFF_X3))[i] = bo[i];

    const int rb = blockIdx.x * 128;
    for (int r = wid; r < 128; r += 8) {
        const float* row = g_pooled + (size_t)(rb + r) * HH;
        int c0 = lid * 4;
        float4 x = *reinterpret_cast<const float4*>(row + c0);
        uint2 hv, lv;
        split2(x.x, x.y, hv.x, lv.x);
        split2(x.z, x.w, hv.y, lv.y);
        uint32_t a = SWZ(r, c0);
        *reinterpret_cast<uint2*>(sm8 + DOFF_AH + a) = hv;
        *reinterpret_cast<uint2*>(sm8 + DOFF_AL + a) = lv;
    }
    __syncthreads();

    float acc[2][8][4];
#pragma unroll
    for (int i = 0; i < 2; i++)
#pragma unroll
        for (int j = 0; j < 8; j++)
#pragma unroll
            for (int c = 0; c < 4; c++) acc[i][j][c] = 0.f;
    {
        const uint32_t pa[3] = {DOFF_AH, DOFF_AH, DOFF_AL};
        const uint32_t pw[3] = {DOFF_WH, DOFF_WL, DOFF_WH};
#pragma unroll 1
        for (int p = 0; p < 3; p++)
            gemm128(smb, pa[p], pw[p], acc, warp_m, warp_n, lid);
    }

    const float* bos = (const float*)(sm8 + DOFF_X3);
#pragma unroll
    for (int mt = 0; mt < 2; mt++) {
        int row0 = warp_m * 32 + mt * 16 + (lid >> 2);
        int row1 = row0 + 8;
#pragma unroll
        for (int nt = 0; nt < 8; nt++) {
            int col = warp_n * 64 + nt * 8 + ((lid & 3) << 1);
            float2 BB = *reinterpret_cast<const float2*>(bos + col);
            size_t o0 = (size_t)(rb + row0) * DD + col;
            size_t o1 = (size_t)(rb + row1) * DD + col;
            g_interp[o0]     = src[o0]     + BB.x + acc[mt][nt][0];
            g_interp[o0 + 1] = src[o0 + 1] + BB.y + acc[mt][nt][1];
            g_interp[o1]     = src[o1]     + BB.x + acc[mt][nt][2];
            g_interp[o1 + 1] = src[o1 + 1] + BB.y + acc[mt][nt][3];
        }
    }
    // column 128 (fp32 dot product, 2 threads per row)
    {
        const float* w128 = (const float*)(sm8 + DOFF_X1);
        int r = tid >> 1, h = tid & 1;
        const float* pr = g_pooled + (size_t)(rb + r) * HH + h * 64;
        float s = 0.f;
#pragma unroll 4
        for (int j = 0; j < 64; j++) s = fmaf(pr[j], w128[h * 64 + j], s);
        s += __shfl_xor_sync(0xffffffffu, s, 1);
        if (h == 0) {
            size_t o = (size_t)(rb + r) * DD + 128;
            g_interp[o] = src[o] + bos[128] + s;
        }
    }
}

// ---------------------------------------------------------------------------
// Tensor-core (HMMA) edge kernel with in-tile segment-max reduction.
// ---------------------------------------------------------------------------
__global__ void __launch_bounds__(256, 1)
edge_tc_kernel(const float* __restrict__ src,
               const float* __restrict__ add_info,
               const int*   __restrict__ nbr_idx,
               const int*   __restrict__ self_idx,
               const float* __restrict__ W1,
               const float* __restrict__ W2,
               const float* __restrict__ b2)
{
    extern __shared__ char sm8[];
    const uint32_t smb = smem_u32(sm8);
    const int tid = threadIdx.x;
    const int wid = tid >> 5, lid = tid & 31;
    const int warp_m = wid >> 1;
    const int warp_n = wid & 1;

    // ---- stage weights ----
    for (int idx = tid; idx < HH * HH; idx += 256) {
        int h = idx & 127, k = idx >> 7;
        float w1 = W1[idx];
        float w2 = W2[idx];
        uint32_t a = SWZ(h, k);
        __nv_bfloat16 w1h = __float2bfloat16_rn(w1);
        __nv_bfloat16 w2h = __float2bfloat16_rn(w2);
        __nv_bfloat16 w1l = __float2bfloat16_rn(w1 - __bfloat162float(w1h));
        __nv_bfloat16 w2l = __float2bfloat16_rn(w2 - __bfloat162float(w2h));
        *reinterpret_cast<__nv_bfloat16*>(sm8 + OFF_W1H + a) = w1h;
        *reinterpret_cast<__nv_bfloat16*>(sm8 + OFF_W1L + a) = w1l;
        *reinterpret_cast<__nv_bfloat16*>(sm8 + OFF_W2H + a) = w2h;
        *reinterpret_cast<__nv_bfloat16*>(sm8 + OFF_W2L + a) = w2l;
    }
    if (tid < 128) {
        ((float*)(sm8 + OFF_W128))[tid] = W1[128 * HH + tid];
        ((float*)(sm8 + OFF_W258))[tid] = W1[258 * HH + tid];
        ((float*)(sm8 + OFF_B2))[tid]   = b2[tid];
    }
    __syncthreads();

    const float* w128s = (const float*)(sm8 + OFF_W128);
    const float* w258s = (const float*)(sm8 + OFF_W258);
    const float* b2s   = (const float*)(sm8 + OFF_B2);
    const int*   selfs = (const int*)(sm8 + OFF_SELF);
    const float* c128s = (const float*)(sm8 + OFF_C128);
    const float* ious  = (const float*)(sm8 + OFF_IOU);
    float* V = (float*)(sm8 + OFF_AH);   // fp32 V tile aliases AH+AL

    for (int tile = blockIdx.x; tile < NTILES; tile += gridDim.x) {
        const int t0 = tile * 128;
        __syncthreads();   // previous tile fully consumed

        // ---- gather A: 128 edges x 128 feats, hi/lo split ----
        for (int r = wid; r < 128; r += 8) {
            int nb = __ldg(&nbr_idx[t0 + r]);
            const float* row = src + (size_t)nb * DD;
            int c0 = lid * 4;
            float x0 = __ldg(row + c0 + 0);
            float x1 = __ldg(row + c0 + 1);
            float x2 = __ldg(row + c0 + 2);
            float x3 = __ldg(row + c0 + 3);
            uint2 hv, lv;
            split2(x0, x1, hv.x, lv.x);
            split2(x2, x3, hv.y, lv.y);
            uint32_t a = SWZ(r, c0);
            *reinterpret_cast<uint2*>(sm8 + OFF_AH + a) = hv;
            *reinterpret_cast<uint2*>(sm8 + OFF_AL + a) = lv;
            if (lid == 0) {
                ((int*)(sm8 + OFF_SELF))[r]   = __ldg(&self_idx[t0 + r]);
                ((float*)(sm8 + OFF_C128))[r] = __ldg(row + 128);
                ((float*)(sm8 + OFF_IOU))[r]  = __ldg(&add_info[t0 + r]);
            }
        }
        __syncthreads();

        // ---- layer-1 GEMM (3 bf16 passes) ----
        float acc[2][8][4];
#pragma unroll
        for (int i = 0; i < 2; i++)
#pragma unroll
            for (int j = 0; j < 8; j++)
#pragma unroll
                for (int c = 0; c < 4; c++) acc[i][j][c] = 0.f;
        {
            const uint32_t pa[3] = {OFF_AH, OFF_AH, OFF_AL};
            const uint32_t pw[3] = {OFF_W1H, OFF_W1L, OFF_W1H};
#pragma unroll 1
            for (int p = 0; p < 3; p++)
                gemm128(smb, pa[p], pw[p], acc, warp_m, warp_n, lid);
        }
        __syncthreads();   // all reads of A done before H overwrites

        // ---- epilogue 1: finish layer-1, relu, restage H (hi/lo) ----
#pragma unroll
        for (int mt = 0; mt < 2; mt++) {
            int row0 = warp_m * 32 + mt * 16 + (lid >> 2);
            int row1 = row0 + 8;
            int s0 = selfs[row0], s1 = selfs[row1];
            float cA0 = c128s[row0], cA1 = c128s[row1];
            float iv0 = ious[row0],  iv1 = ious[row1];
            const float* bp0 = g_base + (size_t)s0 * HH;
            const float* bp1 = g_base + (size_t)s1 * HH;
#pragma unroll
            for (int nt = 0; nt < 8; nt++) {
                int col = warp_n * 64 + nt * 8 + ((lid & 3) << 1);
                float2 B0 = *reinterpret_cast<const float2*>(bp0 + col);
                float2 B1 = *reinterpret_cast<const float2*>(bp1 + col);
                float2 WA = *reinterpret_cast<const float2*>(w128s + col);
                float2 WI = *reinterpret_cast<const float2*>(w258s + col);
                float h00 = fmaxf(acc[mt][nt][0] + B0.x + cA0 * WA.x + iv0 * WI.x, 0.f);
                float h01 = fmaxf(acc[mt][nt][1] + B0.y + cA0 * WA.y + iv0 * WI.y, 0.f);
                float h10 = fmaxf(acc[mt][nt][2] + B1.x + cA1 * WA.x + iv1 * WI.x, 0.f);
                float h11 = fmaxf(acc[mt][nt][3] + B1.y + cA1 * WA.y + iv1 * WI.y, 0.f);
                uint32_t hi, lo;
                split2(h00, h01, hi, lo);
                uint32_t a0 = SWZ(row0, col);
                *reinterpret_cast<uint32_t*>(sm8 + OFF_AH + a0) = hi;
                *reinterpret_cast<uint32_t*>(sm8 + OFF_AL + a0) = lo;
                split2(h10, h11, hi, lo);
                uint32_t a1 = SWZ(row1, col);
                *reinterpret_cast<uint32_t*>(sm8 + OFF_AH + a1) = hi;
                *reinterpret_cast<uint32_t*>(sm8 + OFF_AL + a1) = lo;
            }
        }
        __syncthreads();

        // ---- layer-2 GEMM (3 bf16 passes) ----
#pragma unroll
        for (int i = 0; i < 2; i++)
#pragma unroll
            for (int j = 0; j < 8; j++)
#pragma unroll
                for (int c = 0; c < 4; c++) acc[i][j][c] = 0.f;
        {
            const uint32_t pa[3] = {OFF_AH, OFF_AH, OFF_AL};
            const uint32_t pw[3] = {OFF_W2H, OFF_W2L, OFF_W2H};
#pragma unroll 1
            for (int p = 0; p < 3; p++)
                gemm128(smb, pa[p], pw[p], acc, warp_m, warp_n, lid);
        }
        __syncthreads();   // all reads of H done before V overwrites

        // ---- epilogue 2: bias + relu -> V (smem) ----
#pragma unroll
        for (int mt = 0; mt < 2; mt++) {
            int row0 = warp_m * 32 + mt * 16 + (lid >> 2);
            int row1 = row0 + 8;
#pragma unroll
            for (int nt = 0; nt < 8; nt++) {
                int col = warp_n * 64 + nt * 8 + ((lid & 3) << 1);
                float2 BB = *reinterpret_cast<const float2*>(b2s + col);
                float2 v0, v1;
                v0.x = fmaxf(acc[mt][nt][0] + BB.x, 0.f);
                v0.y = fmaxf(acc[mt][nt][1] + BB.y, 0.f);
                v1.x = fmaxf(acc[mt][nt][2] + BB.x, 0.f);
                v1.y = fmaxf(acc[mt][nt][3] + BB.y, 0.f);
                *reinterpret_cast<float2*>(V + VOFF(row0, col)) = v0;
                *reinterpret_cast<float2*>(V + VOFF(row1, col)) = v1;
            }
        }
        __syncthreads();

        // ---- in-tile segment max over columns, then one atomic per segment ----
        {
            const int c   = tid & 127;
            const int rr0 = (tid >> 7) * 64;
            int cur = selfs[rr0];
            float mxv = 0.f;
#pragma unroll 4
            for (int r = rr0; r < rr0 + 64; ++r) {
                int s = selfs[r];
                if (s != cur) {
                    atomicMax(reinterpret_cast<int*>(g_pooled) + (size_t)cur * HH + c,
                              __float_as_int(mxv));
                    mxv = 0.f;
                    cur = s;
                }
                mxv = fmaxf(mxv, V[VOFF(r, c)]);
            }
            atomicMax(reinterpret_cast<int*>(g_pooled) + (size_t)cur * HH + c,
                      __float_as_int(mxv));
        }
    }
}

// ---------------------------------------------------------------------------
// out[n] = relu(g_interp[n] @ fW1 + fb1) @ fW2 + fb2   (129 -> 64 -> 1)
// ---------------------------------------------------------------------------
__global__ void __launch_bounds__(256)
final_kernel(const float* __restrict__ fW1, const float* __restrict__ fb1,
             const float* __restrict__ fW2, const float* __restrict__ fb2,
             float* __restrict__ out)
{
    __shared__ float W1s[DD * 64];
    __shared__ float w2s[64];
    __shared__ float b1s[64];
    int tid = threadIdx.x;
    for (int i = tid; i < DD * 64; i += 256) W1s[i] = fW1[i];
    if (tid < 64) { w2s[tid] = fW2[tid]; b1s[tid] = fb1[tid]; }
    __syncthreads();
    float fb2v = fb2[0];
    int warp = tid >> 5, lane = tid & 31;
    int n = blockIdx.x * 8 + warp;
    if (n >= NN) return;
    const float* row = g_interp + (size_t)n * DD;
    float h0 = b1s[lane], h1 = b1s[lane + 32];
    for (int k = 0; k < DD; k++) {
        float x = row[k];
        h0 = fmaf(x, W1s[k * 64 + lane],      h0);
        h1 = fmaf(x, W1s[k * 64 + lane + 32], h1);
    }
    float v = fmaxf(h0, 0.f) * w2s[lane] + fmaxf(h1, 0.f) * w2s[lane + 32];
#pragma unroll
    for (int off = 16; off; off >>= 1)
        v += __shfl_down_sync(0xffffffffu, v, off);
    if (lane == 0) out[n] = v + fb2v;
}

// ---------------------------------------------------------------------------
extern "C" void kernel_launch(void* const* d_in, const int* in_sizes, int n_in,
                              void* d_out, int out_size)
{
    (void)in_sizes; (void)n_in; (void)out_size;

    const float* interp_in = (const float*)d_in[0];
    const float* add_info  = (const float*)d_in[1];
    const int*   nbr       = (const int*)d_in[3];
    const int*   self      = (const int*)d_in[4];
    const float* b0W1 = (const float*)d_in[5];
    const float* b0b1 = (const float*)d_in[6];
    const float* b0W2 = (const float*)d_in[7];
    const float* b0b2 = (const float*)d_in[8];
    const float* b0Wo = (const float*)d_in[9];
    const float* b0bo = (const float*)d_in[10];
    const float* b1W1 = (const float*)d_in[11];
    const float* b1b1 = (const float*)d_in[12];
    const float* b1W2 = (const float*)d_in[13];
    const float* b1b2 = (const float*)d_in[14];
    const float* b1Wo = (const float*)d_in[15];
    const float* b1bo = (const float*)d_in[16];
    const float* fW1  = (const float*)d_in[17];
    const float* fb1  = (const float*)d_in[18];
    const float* fW2  = (const float*)d_in[19];
    const float* fb2  = (const float*)d_in[20];
    float* out = (float*)d_out;

    float* ginterp = nullptr;
    cudaGetSymbolAddress((void**)&ginterp, g_interp);
    float* gpooled = nullptr;
    cudaGetSymbolAddress((void**)&gpooled, g_pooled);

    int nsm = 148;
    cudaDeviceGetAttribute(&nsm, cudaDevAttrMultiProcessorCount, 0);

    cudaFuncSetAttribute(edge_tc_kernel,
                         cudaFuncAttributeMaxDynamicSharedMemorySize,
                         (int)SMEM_EDGE);
    cudaFuncSetAttribute(base_hmma,
                         cudaFuncAttributeMaxDynamicSharedMemorySize,
                         (int)SMEM_DENSE);
    cudaFuncSetAttribute(wo_hmma,
                         cudaFuncAttributeMaxDynamicSharedMemorySize,
                         (int)SMEM_DENSE);

    const size_t pooled_bytes = (size_t)NN * HH * sizeof(float);

    // block 0
    cudaMemsetAsync(gpooled, 0, pooled_bytes);
    base_hmma<<<NODTILES, 256, SMEM_DENSE>>>(interp_in, b0W1, b0b1);
    edge_tc_kernel<<<nsm, 256, SMEM_EDGE>>>(interp_in, add_info, nbr, self,
                                            b0W1, b0W2, b0b2);
    wo_hmma<<<NODTILES, 256, SMEM_DENSE>>>(interp_in, b0Wo, b0bo);

    // block 1
    cudaMemsetAsync(gpooled, 0, pooled_bytes);
    base_hmma<<<NODTILES, 256, SMEM_DENSE>>>(ginterp, b1W1, b1b1);
    edge_tc_kernel<<<nsm, 256, SMEM_EDGE>>>(ginterp, add_info, nbr, self,
                                            b1W1, b1W2, b1b2);
    wo_hmma<<<NODTILES, 256, SMEM_DENSE>>>(ginterp, b1Wo, b1bo);

    // final scorer
    final_kernel<<<NN / 8, 256>>>(fW1, fb1, fW2, fb2, out);
}

// round 6
// speedup vs baseline: 4.1913x; 1.0783x over previous
#include <cuda_runtime.h>
#include <cuda_bf16.h>
#include <cstdint>
#include <cstddef>

#define NN 15872
#define DD 129
#define HH 128
#define EE 253952
#define NTILES 1984   // EE / 128 exactly
#define NODTILES 124  // NN / 128 exactly

static __device__ float g_interp[NN * DD];
static __device__ float g_pooled[NN * HH];
static __device__ float g_base[NN * HH];
static __device__ __nv_bfloat16 g_srcH[NN * HH];
static __device__ __nv_bfloat16 g_srcL[NN * HH];

// ---------------------------------------------------------------------------
static __device__ __forceinline__ uint32_t smem_u32(const void* p) {
    uint32_t a;
    asm("{ .reg .u64 t; cvta.to.shared.u64 t, %1; cvt.u32.u64 %0, t; }"
        : "=r"(a) : "l"(p));
    return a;
}

// XOR-swizzled byte offset inside a 128x128 bf16 tile (256B rows, 16B units)
#define SWZ(row, k) ((((uint32_t)(row)) << 8) + \
                     (((((uint32_t)(k) >> 3) ^ ((uint32_t)(row) & 7u))) << 4) + \
                     ((((uint32_t)(k)) & 7u) << 1))

// fp32 V tile word offset (128x128 floats), 16B-unit xor swizzle
#define VOFF(r, c) ((((uint32_t)(r)) << 7) + \
                    (((((uint32_t)(c) >> 2) ^ ((uint32_t)(r) & 7u)) << 2) | \
                     ((uint32_t)(c) & 3u)))

#define LDMATRIX_X4(r0, r1, r2, r3, addr) \
    asm volatile("ldmatrix.sync.aligned.m8n8.x4.shared.b16 {%0,%1,%2,%3}, [%4];" \
                 : "=r"(r0), "=r"(r1), "=r"(r2), "=r"(r3) : "r"(addr))

#define MMA16816(d, a, b0, b1) \
    asm volatile("mma.sync.aligned.m16n8k16.row.col.f32.bf16.bf16.f32 " \
                 "{%0,%1,%2,%3}, {%4,%5,%6,%7}, {%8,%9}, {%0,%1,%2,%3};" \
                 : "+f"((d)[0]), "+f"((d)[1]), "+f"((d)[2]), "+f"((d)[3]) \
                 : "r"((a)[0]), "r"((a)[1]), "r"((a)[2]), "r"((a)[3]), \
                   "r"(b0), "r"(b1))

#define CP_ASYNC16(dst, src) \
    asm volatile("cp.async.cg.shared.global [%0], [%1], 16;" \
                 :: "r"(dst), "l"(src))
#define CP_COMMIT() asm volatile("cp.async.commit_group;")
#define CP_WAIT0()  asm volatile("cp.async.wait_group 0;" ::: "memory")

static __device__ __forceinline__ void split2(float a, float b,
                                              uint32_t& hi, uint32_t& lo) {
    __nv_bfloat16 ah = __float2bfloat16_rn(a);
    __nv_bfloat16 bh = __float2bfloat16_rn(b);
    float ar = a - __bfloat162float(ah);
    float br = b - __bfloat162float(bh);
    __nv_bfloat162 h; h.x = ah; h.y = bh;
    __nv_bfloat162 l = __floats2bfloat162_rn(ar, br);
    hi = *reinterpret_cast<uint32_t*>(&h);
    lo = *reinterpret_cast<uint32_t*>(&l);
}

// ---------------------------------------------------------------------------
// One 128x128x128 bf16 GEMM pass: C += A(offA) @ W(offW)^T, warp tile 32x64.
// ---------------------------------------------------------------------------
static __device__ __forceinline__ void gemm128(uint32_t smb, uint32_t offA,
                                               uint32_t offW,
                                               float (&acc)[2][8][4],
                                               int warp_m, int warp_n, int lid)
{
    const int mi  = lid >> 3;
    const int l7  = lid & 7;
    const int arow_d = l7 + ((mi & 1) << 3);
    const int akk_d  = (mi >> 1) << 3;
    const int brow_d = l7 + ((mi >> 1) << 3);
    const int bkk_d  = (mi & 1) << 3;

#pragma unroll
    for (int ks = 0; ks < 8; ks++) {
        const int k0 = ks * 16;
        uint32_t a[2][4];
#pragma unroll
        for (int mt = 0; mt < 2; mt++) {
            uint32_t ad = smb + offA +
                SWZ(warp_m * 32 + mt * 16 + arow_d, k0 + akk_d);
            LDMATRIX_X4(a[mt][0], a[mt][1], a[mt][2], a[mt][3], ad);
        }
#pragma unroll
        for (int q = 0; q < 4; q++) {
            uint32_t bd = smb + offW +
                SWZ(warp_n * 64 + q * 16 + brow_d, k0 + bkk_d);
            uint32_t b0, b1, b2, b3;
            LDMATRIX_X4(b0, b1, b2, b3, bd);
#pragma unroll
            for (int mt = 0; mt < 2; mt++) {
                MMA16816(acc[mt][2 * q + 0], a[mt], b0, b1);
                MMA16816(acc[mt][2 * q + 1], a[mt], b2, b3);
            }
        }
    }
}

#define ZERO_ACC(acc) \
    { _Pragma("unroll") for (int i_ = 0; i_ < 2; i_++) \
      _Pragma("unroll") for (int j_ = 0; j_ < 8; j_++) \
      _Pragma("unroll") for (int c_ = 0; c_ < 4; c_++) acc[i_][j_][c_] = 0.f; }

// ===========================================================================
// base0: g_base = b1 + src_main @ W1m ; also preconvert src -> g_srcH/L,
// and zero g_pooled.
// smem: WH 0 | WL 32K | AH 64K | AL 96K | w257 @131072 | b1 @131584 | c128 @132096
// ===========================================================================
#define B0_WH 0u
#define B0_WL 32768u
#define B0_AH 65536u
#define B0_AL 98304u
#define B0_W257 131072u
#define B0_B1   131584u
#define B0_C1   132096u
#define SMEM_B0 132608u

__global__ void __launch_bounds__(256, 1)
base0_kernel(const float* __restrict__ src,
             const float* __restrict__ W1,
             const float* __restrict__ b1)
{
    extern __shared__ char sm8[];
    const uint32_t smb = smem_u32(sm8);
    const int tid = threadIdx.x;
    const int wid = tid >> 5, lid = tid & 31;
    const int warp_m = wid >> 1, warp_n = wid & 1;
    const int rb = blockIdx.x * 128;

    for (int idx = tid; idx < HH * HH; idx += 256) {
        int j = idx >> 7, t = idx & 127;
        float w = W1[(129 + j) * HH + t];
        __nv_bfloat16 wh = __float2bfloat16_rn(w);
        __nv_bfloat16 wl = __float2bfloat16_rn(w - __bfloat162float(wh));
        uint32_t a = SWZ(t, j);
        *reinterpret_cast<__nv_bfloat16*>(sm8 + B0_WH + a) = wh;
        *reinterpret_cast<__nv_bfloat16*>(sm8 + B0_WL + a) = wl;
    }
    if (tid < 128) {
        ((float*)(sm8 + B0_W257))[tid] = W1[257 * HH + tid];
        ((float*)(sm8 + B0_B1))[tid]   = b1[tid];
    }
    uint32_t* gsh = reinterpret_cast<uint32_t*>(g_srcH);
    uint32_t* gsl = reinterpret_cast<uint32_t*>(g_srcL);
    for (int r = wid; r < 128; r += 8) {
        const float* row = src + (size_t)(rb + r) * DD;
        int c0 = lid * 4;
        float x0 = __ldg(row + c0 + 0), x1 = __ldg(row + c0 + 1);
        float x2 = __ldg(row + c0 + 2), x3 = __ldg(row + c0 + 3);
        uint2 hv, lv;
        split2(x0, x1, hv.x, lv.x);
        split2(x2, x3, hv.y, lv.y);
        uint32_t a = SWZ(r, c0);
        *reinterpret_cast<uint2*>(sm8 + B0_AH + a) = hv;
        *reinterpret_cast<uint2*>(sm8 + B0_AL + a) = lv;
        size_t gi = ((size_t)(rb + r) * HH + c0) >> 1;
        *reinterpret_cast<uint2*>(&gsh[gi]) = hv;
        *reinterpret_cast<uint2*>(&gsl[gi]) = lv;
        if (lid == 0) ((float*)(sm8 + B0_C1))[r] = __ldg(row + 128);
    }
    // zero pooled rows (no one reads pooled here)
    {
        float4 z = make_float4(0.f, 0.f, 0.f, 0.f);
        float4* gp = reinterpret_cast<float4*>(g_pooled + (size_t)rb * HH);
        for (int i = tid; i < 128 * HH / 4; i += 256) gp[i] = z;
    }
    __syncthreads();

    float acc[2][8][4];
    ZERO_ACC(acc)
    {
        const uint32_t pa[3] = {B0_AH, B0_AH, B0_AL};
        const uint32_t pw[3] = {B0_WH, B0_WL, B0_WH};
#pragma unroll 1
        for (int p = 0; p < 3; p++)
            gemm128(smb, pa[p], pw[p], acc, warp_m, warp_n, lid);
    }

    const float* w7 = (const float*)(sm8 + B0_W257);
    const float* bb = (const float*)(sm8 + B0_B1);
    const float* c1 = (const float*)(sm8 + B0_C1);
#pragma unroll
    for (int mt = 0; mt < 2; mt++) {
        int row0 = warp_m * 32 + mt * 16 + (lid >> 2);
        int row1 = row0 + 8;
        float cv0 = c1[row0], cv1 = c1[row1];
#pragma unroll
        for (int nt = 0; nt < 8; nt++) {
            int col = warp_n * 64 + nt * 8 + ((lid & 3) << 1);
            float2 W7 = *reinterpret_cast<const float2*>(w7 + col);
            float2 BB = *reinterpret_cast<const float2*>(bb + col);
            float2 o0, o1;
            o0.x = acc[mt][nt][0] + BB.x + cv0 * W7.x;
            o0.y = acc[mt][nt][1] + BB.y + cv0 * W7.y;
            o1.x = acc[mt][nt][2] + BB.x + cv1 * W7.x;
            o1.y = acc[mt][nt][3] + BB.y + cv1 * W7.y;
            *reinterpret_cast<float2*>(g_base + (size_t)(rb + row0) * HH + col) = o0;
            *reinterpret_cast<float2*>(g_base + (size_t)(rb + row1) * HH + col) = o1;
        }
    }
}

// ===========================================================================
// edge kernel: cp.async gather from g_srcH/L, 2 GEMM layers, in-tile pooling
// ===========================================================================
#define OFF_AH   0u
#define OFF_AL   32768u
#define OFF_W1H  65536u
#define OFF_W1L  98304u
#define OFF_W2H  131072u
#define OFF_W2L  163840u
#define OFF_SELF 196608u
#define OFF_C128 197120u
#define OFF_IOU  197632u
#define OFF_W128 198144u
#define OFF_W258 198656u
#define OFF_B2   199168u
#define SMEM_EDGE 199680u

__global__ void __launch_bounds__(256, 1)
edge_tc_kernel(const float* __restrict__ src,       // fp32 rows (for col 128)
               const float* __restrict__ add_info,
               const int*   __restrict__ nbr_idx,
               const int*   __restrict__ self_idx,
               const float* __restrict__ W1,
               const float* __restrict__ W2,
               const float* __restrict__ b2)
{
    extern __shared__ char sm8[];
    const uint32_t smb = smem_u32(sm8);
    const int tid = threadIdx.x;
    const int wid = tid >> 5, lid = tid & 31;
    const int warp_m = wid >> 1;
    const int warp_n = wid & 1;

    for (int idx = tid; idx < HH * HH; idx += 256) {
        int h = idx & 127, k = idx >> 7;
        float w1 = W1[idx];
        float w2 = W2[idx];
        uint32_t a = SWZ(h, k);
        __nv_bfloat16 w1h = __float2bfloat16_rn(w1);
        __nv_bfloat16 w2h = __float2bfloat16_rn(w2);
        __nv_bfloat16 w1l = __float2bfloat16_rn(w1 - __bfloat162float(w1h));
        __nv_bfloat16 w2l = __float2bfloat16_rn(w2 - __bfloat162float(w2h));
        *reinterpret_cast<__nv_bfloat16*>(sm8 + OFF_W1H + a) = w1h;
        *reinterpret_cast<__nv_bfloat16*>(sm8 + OFF_W1L + a) = w1l;
        *reinterpret_cast<__nv_bfloat16*>(sm8 + OFF_W2H + a) = w2h;
        *reinterpret_cast<__nv_bfloat16*>(sm8 + OFF_W2L + a) = w2l;
    }
    if (tid < 128) {
        ((float*)(sm8 + OFF_W128))[tid] = W1[128 * HH + tid];
        ((float*)(sm8 + OFF_W258))[tid] = W1[258 * HH + tid];
        ((float*)(sm8 + OFF_B2))[tid]   = b2[tid];
    }
    __syncthreads();

    const float* w128s = (const float*)(sm8 + OFF_W128);
    const float* w258s = (const float*)(sm8 + OFF_W258);
    const float* b2s   = (const float*)(sm8 + OFF_B2);
    const int*   selfs = (const int*)(sm8 + OFF_SELF);
    const float* c128s = (const float*)(sm8 + OFF_C128);
    const float* ious  = (const float*)(sm8 + OFF_IOU);
    float* V = (float*)(sm8 + OFF_AH);   // fp32 V tile aliases AH+AL

    const int grow = tid >> 1;          // 0..127
    const int half = tid & 1;           // 0: hi, 1: lo
    const __nv_bfloat16* gsrc = half ? g_srcL : g_srcH;
    const uint32_t dstbase0 = smb + (half ? OFF_AL : OFF_AH) +
                              ((uint32_t)grow << 8);
    const uint32_t grx = (uint32_t)(grow & 7);

    for (int tile = blockIdx.x; tile < NTILES; tile += gridDim.x) {
        const int t0 = tile * 128;
        __syncthreads();   // previous tile fully consumed

        // ---- gather A via cp.async (16 x 16B per thread) ----
        {
            int nb = __ldg(&nbr_idx[t0 + grow]);
            const __nv_bfloat16* rowp = gsrc + ((size_t)nb << 7);
            if (half == 0) {
                ((int*)(sm8 + OFF_SELF))[grow]   = __ldg(&self_idx[t0 + grow]);
                ((float*)(sm8 + OFF_C128))[grow] = __ldg(&src[(size_t)nb * DD + 128]);
                ((float*)(sm8 + OFF_IOU))[grow]  = __ldg(&add_info[t0 + grow]);
            }
#pragma unroll
            for (uint32_t u = 0; u < 16; u++) {
                uint32_t dst = dstbase0 + ((u ^ grx) << 4);
                CP_ASYNC16(dst, rowp + u * 8);
            }
            CP_COMMIT();
            CP_WAIT0();
        }
        __syncthreads();

        // ---- layer-1 GEMM (3 bf16 passes) ----
        float acc[2][8][4];
        ZERO_ACC(acc)
        {
            const uint32_t pa[3] = {OFF_AH, OFF_AH, OFF_AL};
            const uint32_t pw[3] = {OFF_W1H, OFF_W1L, OFF_W1H};
#pragma unroll 1
            for (int p = 0; p < 3; p++)
                gemm128(smb, pa[p], pw[p], acc, warp_m, warp_n, lid);
        }
        __syncthreads();

        // ---- epilogue 1: finish layer-1, relu, restage H (hi/lo) ----
#pragma unroll
        for (int mt = 0; mt < 2; mt++) {
            int row0 = warp_m * 32 + mt * 16 + (lid >> 2);
            int row1 = row0 + 8;
            int s0 = selfs[row0], s1 = selfs[row1];
            float cA0 = c128s[row0], cA1 = c128s[row1];
            float iv0 = ious[row0],  iv1 = ious[row1];
            const float* bp0 = g_base + (size_t)s0 * HH;
            const float* bp1 = g_base + (size_t)s1 * HH;
#pragma unroll
            for (int nt = 0; nt < 8; nt++) {
                int col = warp_n * 64 + nt * 8 + ((lid & 3) << 1);
                float2 B0 = *reinterpret_cast<const float2*>(bp0 + col);
                float2 B1 = *reinterpret_cast<const float2*>(bp1 + col);
                float2 WA = *reinterpret_cast<const float2*>(w128s + col);
                float2 WI = *reinterpret_cast<const float2*>(w258s + col);
                float h00 = fmaxf(acc[mt][nt][0] + B0.x + cA0 * WA.x + iv0 * WI.x, 0.f);
                float h01 = fmaxf(acc[mt][nt][1] + B0.y + cA0 * WA.y + iv0 * WI.y, 0.f);
                float h10 = fmaxf(acc[mt][nt][2] + B1.x + cA1 * WA.x + iv1 * WI.x, 0.f);
                float h11 = fmaxf(acc[mt][nt][3] + B1.y + cA1 * WA.y + iv1 * WI.y, 0.f);
                uint32_t hi, lo;
                split2(h00, h01, hi, lo);
                uint32_t a0 = SWZ(row0, col);
                *reinterpret_cast<uint32_t*>(sm8 + OFF_AH + a0) = hi;
                *reinterpret_cast<uint32_t*>(sm8 + OFF_AL + a0) = lo;
                split2(h10, h11, hi, lo);
                uint32_t a1 = SWZ(row1, col);
                *reinterpret_cast<uint32_t*>(sm8 + OFF_AH + a1) = hi;
                *reinterpret_cast<uint32_t*>(sm8 + OFF_AL + a1) = lo;
            }
        }
        __syncthreads();

        // ---- layer-2 GEMM (3 bf16 passes) ----
        ZERO_ACC(acc)
        {
            const uint32_t pa[3] = {OFF_AH, OFF_AH, OFF_AL};
            const uint32_t pw[3] = {OFF_W2H, OFF_W2L, OFF_W2H};
#pragma unroll 1
            for (int p = 0; p < 3; p++)
                gemm128(smb, pa[p], pw[p], acc, warp_m, warp_n, lid);
        }
        __syncthreads();

        // ---- epilogue 2: bias + relu -> V (smem) ----
#pragma unroll
        for (int mt = 0; mt < 2; mt++) {
            int row0 = warp_m * 32 + mt * 16 + (lid >> 2);
            int row1 = row0 + 8;
#pragma unroll
            for (int nt = 0; nt < 8; nt++) {
                int col = warp_n * 64 + nt * 8 + ((lid & 3) << 1);
                float2 BB = *reinterpret_cast<const float2*>(b2s + col);
                float2 v0, v1;
                v0.x = fmaxf(acc[mt][nt][0] + BB.x, 0.f);
                v0.y = fmaxf(acc[mt][nt][1] + BB.y, 0.f);
                v1.x = fmaxf(acc[mt][nt][2] + BB.x, 0.f);
                v1.y = fmaxf(acc[mt][nt][3] + BB.y, 0.f);
                *reinterpret_cast<float2*>(V + VOFF(row0, col)) = v0;
                *reinterpret_cast<float2*>(V + VOFF(row1, col)) = v1;
            }
        }
        __syncthreads();

        // ---- in-tile segment max, one atomic per (segment,col) ----
        {
            const int c   = tid & 127;
            const int rr0 = (tid >> 7) * 64;
            int cur = selfs[rr0];
            float mxv = 0.f;
#pragma unroll 4
            for (int r = rr0; r < rr0 + 64; ++r) {
                int s = selfs[r];
                if (s != cur) {
                    atomicMax(reinterpret_cast<int*>(g_pooled) + (size_t)cur * HH + c,
                              __float_as_int(mxv));
                    mxv = 0.f;
                    cur = s;
                }
                mxv = fmaxf(mxv, V[VOFF(r, c)]);
            }
            atomicMax(reinterpret_cast<int*>(g_pooled) + (size_t)cur * HH + c,
                      __float_as_int(mxv));
        }
    }
}

// ===========================================================================
// wobase: interp1 = src + bo0 + pooled @ Wo0 (write g_interp, g_srcH/L),
//         then g_base = b1_1 + interp1_main @ W1m_1 ; zero g_pooled.
// ===========================================================================
#define WB_WOH 0u
#define WB_WOL 32768u
#define WB_W1H 65536u
#define WB_W1L 98304u
#define WB_AH  131072u
#define WB_AL  163840u
#define WB_BO  196608u   // 129 f (pad 544)
#define WB_B1  197152u   // 128 f
#define WB_W257 197664u
#define WB_WOC 198176u   // Wo col 128 (128 f)
#define WB_C1  198688u   // interp col128 per row
#define SMEM_WB 199200u

__global__ void __launch_bounds__(256, 1)
wobase_kernel(const float* __restrict__ src,    // interp_in
              const float* __restrict__ Wo,     // block0 (128 x 129)
              const float* __restrict__ bo,     // block0 (129)
              const float* __restrict__ W1b,    // block1 W1 (259 x 128)
              const float* __restrict__ b1b)    // block1 b1 (128)
{
    extern __shared__ char sm8[];
    const uint32_t smb = smem_u32(sm8);
    const int tid = threadIdx.x;
    const int wid = tid >> 5, lid = tid & 31;
    const int warp_m = wid >> 1, warp_n = wid & 1;
    const int rb = blockIdx.x * 128;

    // stage weights
    for (int idx = tid; idx < HH * HH; idx += 256) {
        int j = idx >> 7, c = idx & 127;
        float w = Wo[j * DD + c];
        __nv_bfloat16 wh = __float2bfloat16_rn(w);
        __nv_bfloat16 wl = __float2bfloat16_rn(w - __bfloat162float(wh));
        uint32_t a = SWZ(c, j);
        *reinterpret_cast<__nv_bfloat16*>(sm8 + WB_WOH + a) = wh;
        *reinterpret_cast<__nv_bfloat16*>(sm8 + WB_WOL + a) = wl;
        float w1 = W1b[(129 + j) * HH + c];
        __nv_bfloat16 w1h = __float2bfloat16_rn(w1);
        __nv_bfloat16 w1l = __float2bfloat16_rn(w1 - __bfloat162float(w1h));
        *reinterpret_cast<__nv_bfloat16*>(sm8 + WB_W1H + a) = w1h;   // SWZ(t=c,j)
        *reinterpret_cast<__nv_bfloat16*>(sm8 + WB_W1L + a) = w1l;
    }
    if (tid < 128) {
        ((float*)(sm8 + WB_WOC))[tid]  = Wo[tid * DD + 128];
        ((float*)(sm8 + WB_W257))[tid] = W1b[257 * HH + tid];
        ((float*)(sm8 + WB_B1))[tid]   = b1b[tid];
    }
    for (int i = tid; i < DD; i += 256) ((float*)(sm8 + WB_BO))[i] = bo[i];
    __syncthreads();

    // A stage: pooled -> bf16 hi/lo
    for (int r = wid; r < 128; r += 8) {
        const float* prow = g_pooled + (size_t)(rb + r) * HH;
        int c0 = lid * 4;
        float4 x = *reinterpret_cast<const float4*>(prow + c0);
        uint2 hv, lv;
        split2(x.x, x.y, hv.x, lv.x);
        split2(x.z, x.w, hv.y, lv.y);
        uint32_t a = SWZ(r, c0);
        *reinterpret_cast<uint2*>(sm8 + WB_AH + a) = hv;
        *reinterpret_cast<uint2*>(sm8 + WB_AL + a) = lv;
    }
    // col 128 of interp1 (fp32 dot) + residual + bias
    {
        const float* wocol = (const float*)(sm8 + WB_WOC);
        const float* bos   = (const float*)(sm8 + WB_BO);
        int r = tid >> 1, h = tid & 1;
        const float* prow = g_pooled + (size_t)(rb + r) * HH + h * 64;
        float s = 0.f;
#pragma unroll 4
        for (int j = 0; j < 64; j++) s = fmaf(prow[j], wocol[h * 64 + j], s);
        s += __shfl_xor_sync(0xffffffffu, s, 1);
        if (h == 0) {
            float v = s + __ldg(&src[(size_t)(rb + r) * DD + 128]) + bos[128];
            ((float*)(sm8 + WB_C1))[r] = v;
            g_interp[(size_t)(rb + r) * DD + 128] = v;
        }
    }
    __syncthreads();
    // zero pooled (all reads done)
    {
        float4 z = make_float4(0.f, 0.f, 0.f, 0.f);
        float4* gp = reinterpret_cast<float4*>(g_pooled + (size_t)rb * HH);
        for (int i = tid; i < 128 * HH / 4; i += 256) gp[i] = z;
    }

    // GEMM 1: pooled @ Wo
    float acc[2][8][4];
    ZERO_ACC(acc)
    {
        const uint32_t pa[3] = {WB_AH, WB_AH, WB_AL};
        const uint32_t pw[3] = {WB_WOH, WB_WOL, WB_WOH};
#pragma unroll 1
        for (int p = 0; p < 3; p++)
            gemm128(smb, pa[p], pw[p], acc, warp_m, warp_n, lid);
    }
    __syncthreads();   // A reads done; we overwrite AH/AL with interp1

    // epilogue wo: interp1 = acc + src + bo; write g_interp, g_srcH/L, smem A
    {
        const float* bos = (const float*)(sm8 + WB_BO);
        uint32_t* gsh = reinterpret_cast<uint32_t*>(g_srcH);
        uint32_t* gsl = reinterpret_cast<uint32_t*>(g_srcL);
#pragma unroll
        for (int mt = 0; mt < 2; mt++) {
            int row0 = warp_m * 32 + mt * 16 + (lid >> 2);
            int row1 = row0 + 8;
#pragma unroll
            for (int nt = 0; nt < 8; nt++) {
                int col = warp_n * 64 + nt * 8 + ((lid & 3) << 1);
                float2 BB = *reinterpret_cast<const float2*>(bos + col);
                size_t o0 = (size_t)(rb + row0) * DD + col;
                size_t o1 = (size_t)(rb + row1) * DD + col;
                float i00 = acc[mt][nt][0] + src[o0]     + BB.x;
                float i01 = acc[mt][nt][1] + src[o0 + 1] + BB.y;
                float i10 = acc[mt][nt][2] + src[o1]     + BB.x;
                float i11 = acc[mt][nt][3] + src[o1 + 1] + BB.y;
                g_interp[o0] = i00; g_interp[o0 + 1] = i01;
                g_interp[o1] = i10; g_interp[o1 + 1] = i11;
                uint32_t hi, lo;
                split2(i00, i01, hi, lo);
                uint32_t a0 = SWZ(row0, col);
                *reinterpret_cast<uint32_t*>(sm8 + WB_AH + a0) = hi;
                *reinterpret_cast<uint32_t*>(sm8 + WB_AL + a0) = lo;
                gsh[((size_t)(rb + row0) * HH + col) >> 1] = hi;
                gsl[((size_t)(rb + row0) * HH + col) >> 1] = lo;
                split2(i10, i11, hi, lo);
                uint32_t a1 = SWZ(row1, col);
                *reinterpret_cast<uint32_t*>(sm8 + WB_AH + a1) = hi;
                *reinterpret_cast<uint32_t*>(sm8 + WB_AL + a1) = lo;
                gsh[((size_t)(rb + row1) * HH + col) >> 1] = hi;
                gsl[((size_t)(rb + row1) * HH + col) >> 1] = lo;
            }
        }
    }
    __syncthreads();

    // GEMM 2: interp1 @ W1m (block1) -> g_base
    ZERO_ACC(acc)
    {
        const uint32_t pa[3] = {WB_AH, WB_AH, WB_AL};
        const uint32_t pw[3] = {WB_W1H, WB_W1L, WB_W1H};
#pragma unroll 1
        for (int p = 0; p < 3; p++)
            gemm128(smb, pa[p], pw[p], acc, warp_m, warp_n, lid);
    }
    {
        const float* w7 = (const float*)(sm8 + WB_W257);
        const float* bb = (const float*)(sm8 + WB_B1);
        const float* c1 = (const float*)(sm8 + WB_C1);
#pragma unroll
        for (int mt = 0; mt < 2; mt++) {
            int row0 = warp_m * 32 + mt * 16 + (lid >> 2);
            int row1 = row0 + 8;
            float cv0 = c1[row0], cv1 = c1[row1];
#pragma unroll
            for (int nt = 0; nt < 8; nt++) {
                int col = warp_n * 64 + nt * 8 + ((lid & 3) << 1);
                float2 W7 = *reinterpret_cast<const float2*>(w7 + col);
                float2 BB = *reinterpret_cast<const float2*>(bb + col);
                float2 o0, o1;
                o0.x = acc[mt][nt][0] + BB.x + cv0 * W7.x;
                o0.y = acc[mt][nt][1] + BB.y + cv0 * W7.y;
                o1.x = acc[mt][nt][2] + BB.x + cv1 * W7.x;
                o1.y = acc[mt][nt][3] + BB.y + cv1 * W7.y;
                *reinterpret_cast<float2*>(g_base + (size_t)(rb + row0) * HH + col) = o0;
                *reinterpret_cast<float2*>(g_base + (size_t)(rb + row1) * HH + col) = o1;
            }
        }
    }
}

// ===========================================================================
// wofinal: interp2 = g_interp + bo1 + pooled @ Wo1 (smem only),
//          out = relu(interp2 @ fW1 + fb1) @ fW2 + fb2
// ===========================================================================
#define WF_WOH 0u
#define WF_WOL 32768u
#define WF_AH  65536u            // bf16 A; later fp32 fT (col-major) 64K
#define WF_AL  98304u
#define WF_FW  131072u           // 129*64 f = 33024
#define WF_FB1 164096u           // 64 f
#define WF_FW2 164352u           // 64 f
#define WF_BO  164608u           // 129 f (pad)
#define WF_C1  165152u           // 128 f
#define WF_WOC 165664u           // 128 f
#define SMEM_WF 166176u

__global__ void __launch_bounds__(256, 1)
wofinal_kernel(const float* __restrict__ Wo,    // block1 (128 x 129)
               const float* __restrict__ bo,    // block1 (129)
               const float* __restrict__ fW1, const float* __restrict__ fb1,
               const float* __restrict__ fW2, const float* __restrict__ fb2,
               float* __restrict__ out)
{
    extern __shared__ char sm8[];
    const uint32_t smb = smem_u32(sm8);
    const int tid = threadIdx.x;
    const int wid = tid >> 5, lid = tid & 31;
    const int warp_m = wid >> 1, warp_n = wid & 1;
    const int rb = blockIdx.x * 128;

    for (int idx = tid; idx < HH * HH; idx += 256) {
        int j = idx >> 7, c = idx & 127;
        float w = Wo[j * DD + c];
        __nv_bfloat16 wh = __float2bfloat16_rn(w);
        __nv_bfloat16 wl = __float2bfloat16_rn(w - __bfloat162float(wh));
        uint32_t a = SWZ(c, j);
        *reinterpret_cast<__nv_bfloat16*>(sm8 + WF_WOH + a) = wh;
        *reinterpret_cast<__nv_bfloat16*>(sm8 + WF_WOL + a) = wl;
    }
    if (tid < 128) ((float*)(sm8 + WF_WOC))[tid] = Wo[tid * DD + 128];
    for (int i = tid; i < DD * 64; i += 256) ((float*)(sm8 + WF_FW))[i] = fW1[i];
    if (tid < 64) {
        ((float*)(sm8 + WF_FB1))[tid] = fb1[tid];
        ((float*)(sm8 + WF_FW2))[tid] = fW2[tid];
    }
    for (int i = tid; i < DD; i += 256) ((float*)(sm8 + WF_BO))[i] = bo[i];
    __syncthreads();

    for (int r = wid; r < 128; r += 8) {
        const float* prow = g_pooled + (size_t)(rb + r) * HH;
        int c0 = lid * 4;
        float4 x = *reinterpret_cast<const float4*>(prow + c0);
        uint2 hv, lv;
        split2(x.x, x.y, hv.x, lv.x);
        split2(x.z, x.w, hv.y, lv.y);
        uint32_t a = SWZ(r, c0);
        *reinterpret_cast<uint2*>(sm8 + WF_AH + a) = hv;
        *reinterpret_cast<uint2*>(sm8 + WF_AL + a) = lv;
    }
    {
        const float* wocol = (const float*)(sm8 + WF_WOC);
        const float* bos   = (const float*)(sm8 + WF_BO);
        int r = tid >> 1, h = tid & 1;
        const float* prow = g_pooled + (size_t)(rb + r) * HH + h * 64;
        float s = 0.f;
#pragma unroll 4
        for (int j = 0; j < 64; j++) s = fmaf(prow[j], wocol[h * 64 + j], s);
        s += __shfl_xor_sync(0xffffffffu, s, 1);
        if (h == 0)
            ((float*)(sm8 + WF_C1))[r] =
                s + __ldg(&g_interp[(size_t)(rb + r) * DD + 128]) + bos[128];
    }
    __syncthreads();

    float acc[2][8][4];
    ZERO_ACC(acc)
    {
        const uint32_t pa[3] = {WF_AH, WF_AH, WF_AL};
        const uint32_t pw[3] = {WF_WOH, WF_WOL, WF_WOH};
#pragma unroll 1
        for (int p = 0; p < 3; p++)
            gemm128(smb, pa[p], pw[p], acc, warp_m, warp_n, lid);
    }
    __syncthreads();   // A reads done; overwrite with fp32 fT (col-major)

    {
        const float* bos = (const float*)(sm8 + WF_BO);
        float* fT = (float*)(sm8 + WF_AH);
#pragma unroll
        for (int mt = 0; mt < 2; mt++) {
            int row0 = warp_m * 32 + mt * 16 + (lid >> 2);
            int row1 = row0 + 8;
#pragma unroll
            for (int nt = 0; nt < 8; nt++) {
                int col = warp_n * 64 + nt * 8 + ((lid & 3) << 1);
                float2 BB = *reinterpret_cast<const float2*>(bos + col);
                size_t o0 = (size_t)(rb + row0) * DD + col;
                size_t o1 = (size_t)(rb + row1) * DD + col;
                fT[col * 128 + row0]       = acc[mt][nt][0] + g_interp[o0]     + BB.x;
                fT[(col + 1) * 128 + row0] = acc[mt][nt][1] + g_interp[o0 + 1] + BB.y;
                fT[col * 128 + row1]       = acc[mt][nt][2] + g_interp[o1]     + BB.x;
                fT[(col + 1) * 128 + row1] = acc[mt][nt][3] + g_interp[o1 + 1] + BB.y;
            }
        }
    }
    __syncthreads();

    // final MLP: 2 threads per row
    {
        const float* fT  = (const float*)(sm8 + WF_AH);
        const float* fw1 = (const float*)(sm8 + WF_FW);
        const float* fb1s = (const float*)(sm8 + WF_FB1);
        const float* fw2s = (const float*)(sm8 + WF_FW2);
        const float* c1  = (const float*)(sm8 + WF_C1);
        int r = tid >> 1, h = tid & 1;
        float hacc[32];
#pragma unroll
        for (int u = 0; u < 32; u++) hacc[u] = fb1s[h * 32 + u];
        for (int k = 0; k < 128; k++) {
            float xv = fT[k * 128 + r];
            const float4* wrow = reinterpret_cast<const float4*>(fw1 + k * 64 + h * 32);
#pragma unroll
            for (int u4 = 0; u4 < 8; u4++) {
                float4 w = wrow[u4];
                hacc[u4 * 4 + 0] = fmaf(xv, w.x, hacc[u4 * 4 + 0]);
                hacc[u4 * 4 + 1] = fmaf(xv, w.y, hacc[u4 * 4 + 1]);
                hacc[u4 * 4 + 2] = fmaf(xv, w.z, hacc[u4 * 4 + 2]);
                hacc[u4 * 4 + 3] = fmaf(xv, w.w, hacc[u4 * 4 + 3]);
            }
        }
        {
            float xv = c1[r];
            const float4* wrow = reinterpret_cast<const float4*>(fw1 + 128 * 64 + h * 32);
#pragma unroll
            for (int u4 = 0; u4 < 8; u4++) {
                float4 w = wrow[u4];
                hacc[u4 * 4 + 0] = fmaf(xv, w.x, hacc[u4 * 4 + 0]);
                hacc[u4 * 4 + 1] = fmaf(xv, w.y, hacc[u4 * 4 + 1]);
                hacc[u4 * 4 + 2] = fmaf(xv, w.z, hacc[u4 * 4 + 2]);
                hacc[u4 * 4 + 3] = fmaf(xv, w.w, hacc[u4 * 4 + 3]);
            }
        }
        float v = 0.f;
#pragma unroll
        for (int u = 0; u < 32; u++)
            v = fmaf(fmaxf(hacc[u], 0.f), fw2s[h * 32 + u], v);
        v += __shfl_xor_sync(0xffffffffu, v, 1);
        if (h == 0) out[rb + r] = v + __ldg(fb2);
    }
}

// ---------------------------------------------------------------------------
extern "C" void kernel_launch(void* const* d_in, const int* in_sizes, int n_in,
                              void* d_out, int out_size)
{
    (void)in_sizes; (void)n_in; (void)out_size;

    const float* interp_in = (const float*)d_in[0];
    const float* add_info  = (const float*)d_in[1];
    const int*   nbr       = (const int*)d_in[3];
    const int*   self      = (const int*)d_in[4];
    const float* b0W1 = (const float*)d_in[5];
    const float* b0b1 = (const float*)d_in[6];
    const float* b0W2 = (const float*)d_in[7];
    const float* b0b2 = (const float*)d_in[8];
    const float* b0Wo = (const float*)d_in[9];
    const float* b0bo = (const float*)d_in[10];
    const float* b1W1 = (const float*)d_in[11];
    const float* b1b1 = (const float*)d_in[12];
    const float* b1W2 = (const float*)d_in[13];
    const float* b1b2 = (const float*)d_in[14];
    const float* b1Wo = (const float*)d_in[15];
    const float* b1bo = (const float*)d_in[16];
    const float* fW1  = (const float*)d_in[17];
    const float* fb1  = (const float*)d_in[18];
    const float* fW2  = (const float*)d_in[19];
    const float* fb2  = (const float*)d_in[20];
    float* out = (float*)d_out;

    float* ginterp = nullptr;
    cudaGetSymbolAddress((void**)&ginterp, g_interp);

    int nsm = 148;
    cudaDeviceGetAttribute(&nsm, cudaDevAttrMultiProcessorCount, 0);

    cudaFuncSetAttribute(base0_kernel,
        cudaFuncAttributeMaxDynamicSharedMemorySize, (int)SMEM_B0);
    cudaFuncSetAttribute(edge_tc_kernel,
        cudaFuncAttributeMaxDynamicSharedMemorySize, (int)SMEM_EDGE);
    cudaFuncSetAttribute(wobase_kernel,
        cudaFuncAttributeMaxDynamicSharedMemorySize, (int)SMEM_WB);
    cudaFuncSetAttribute(wofinal_kernel,
        cudaFuncAttributeMaxDynamicSharedMemorySize, (int)SMEM_WF);

    base0_kernel<<<NODTILES, 256, SMEM_B0>>>(interp_in, b0W1, b0b1);
    edge_tc_kernel<<<nsm, 256, SMEM_EDGE>>>(interp_in, add_info, nbr, self,
                                            b0W1, b0W2, b0b2);
    wobase_kernel<<<NODTILES, 256, SMEM_WB>>>(interp_in, b0Wo, b0bo,
                                              b1W1, b1b1);
    edge_tc_kernel<<<nsm, 256, SMEM_EDGE>>>(ginterp, add_info, nbr, self,
                                            b1W1, b1W2, b1b2);
    wofinal_kernel<<<NODTILES, 256, SMEM_WF>>>(b1Wo, b1bo, fW1, fb1,
                                               fW2, fb2, out);
}